// round 11
// baseline (speedup 1.0000x reference)
#include <cuda_runtime.h>
#include <cuda_bf16.h>
#include <math.h>

// Problem constants
#define BSZ 128
#define SSZ 256
#define ESZ 300
#define HSZ 512
#define G4  2048           // 4*H
#define NB_RECUR 128       // persistent kernel grid (<= 148 SMs -> co-resident wave 1)

// ---------------- scratch (static device memory; no runtime allocation) -----
// PRE1 aliases PRE0F (l0-fwd pre fully consumed before l1 projection runs).
// All [t][r] tensors are stored in RANK-permuted batch order (r = rank).
__device__ float PRE0F[SSZ * BSZ * G4];          // [t][r][4H] l0 fwd  (later: l1 rev)
__device__ float PRE0R[SSZ * BSZ * G4];          // [t][r][4H] l0 rev
__device__ float OUT0 [SSZ * BSZ * 2 * HSZ];     // [t][r][2H] concat(fwd,rev)
__device__ float HBUF [9][BSZ * HSZ];            // h double-buffers (rank-permuted rows)
__device__ int   LEN[BSZ];
__device__ int   RANK[BSZ];                      // original b -> rank (desc by length)
__device__ int   NACT[SSZ];                      // #rows with len > t
__device__ unsigned int BAR_CNT;
__device__ volatile unsigned int BAR_GEN;

__device__ __forceinline__ float sigm(float x) { return 1.0f / (1.0f + expf(-x)); }

// ---------------- init: lengths, ones-init h buffers, barrier reset ---------
__global__ void k_init(const float* __restrict__ x) {
    int tid = blockIdx.x * blockDim.x + threadIdx.x;
    const int slab = BSZ * HSZ;                   // 65536
    if (tid < 3 * slab) {                         // ones-init h bufs 0, 3, 6
        int w = tid / slab, i = tid - w * slab;
        HBUF[w * 3][i] = 1.0f;
    }
    if (tid < BSZ) {
        int v = (int)x[((size_t)tid * SSZ + (SSZ - 1)) * ESZ];  // x[b, S-1, 0]
        LEN[tid] = v < SSZ ? v : SSZ;
    }
    if (tid == 0) { BAR_CNT = 0; BAR_GEN = 0; }
}

__global__ void k_reset() { BAR_CNT = 0; BAR_GEN = 0; }

// ---------------- prep: rank permutation (desc length, stable) + NACT -------
__global__ void k_prep() {
    __shared__ int sl[BSZ];
    int b = threadIdx.x;            // 128 threads
    sl[b] = LEN[b];
    __syncthreads();
    int mylen = sl[b];
    int rk = 0;
    for (int o = 0; o < BSZ; o++) {
        int lo = sl[o];
        rk += (lo > mylen) || (lo == mylen && o < b);
    }
    RANK[b] = rk;
    for (int t = b; t < SSZ; t += BSZ) {
        int c = 0;
        for (int o = 0; o < BSZ; o++) c += (sl[o] > t);
        NACT[t] = c;
    }
}

// ---------------- tensor-core NT-GEMM (bf16 hi/lo split precision) ----------
// C[M,2048] = A[M,K] * W[2048,K]^T + b1 + b2, computed as
//   Ahi*Bhi + Ahi*Blo + Alo*Bhi   (3x mma.m16n8k16.bf16, ~fp32-accurate)
// Block tile 128x64, BK=32, 256 threads = 8 warps (4 m-warps x 2 n-warps),
// warp tile 32x32 = 2 m16-tiles x 4 n8-tiles.
// mode 1: layer-0 projection. A rows = b*S+t; out row = t*128 + RANK[b];
//         row-activity rowlim = LEN[b]-t0 (tile spans one b).
// mode 2: layer-1 projection. A rows = t*128+r; out row = m; rowlim = NACT[t].
#define MMA_BF16(C, A0, A1, A2, A3, B0, B1)                                   \
    asm volatile("mma.sync.aligned.m16n8k16.row.col.f32.bf16.bf16.f32 "       \
                 "{%0,%1,%2,%3}, {%4,%5,%6,%7}, {%8,%9}, {%0,%1,%2,%3};"      \
                 : "+f"((C)[0]), "+f"((C)[1]), "+f"((C)[2]), "+f"((C)[3])     \
                 : "r"(A0), "r"(A1), "r"(A2), "r"(A3), "r"(B0), "r"(B1))

__global__ void __launch_bounds__(256, 2) k_gemm_tc(
    const float* __restrict__ A, int M, int K,
    const float* __restrict__ W,
    const float* __restrict__ b1, const float* __restrict__ b2,
    float* __restrict__ C, int mode)
{
    // stride 40 bf16 = 20 u32 words per row -> conflict-free fragment loads
    __shared__ unsigned Ah[128 * 20], Al[128 * 20];
    __shared__ unsigned Bh[64 * 20],  Bl[64 * 20];

    int tid  = threadIdx.x;
    int warp = tid >> 5, lane = tid & 31;
    int wm = warp >> 1, wn = warp & 1;          // 4 x 2 warp grid
    int lr = lane >> 2, lc = lane & 3;
    int mbase = blockIdx.y * 128;
    int nbase = blockIdx.x * 64;

    int rowlim = 128;
    if (mode == 1) {
        int b = mbase >> 8, t0 = mbase & 255;
        rowlim = LEN[b] - t0;
        if (rowlim > 128) rowlim = 128;
        if (rowlim <= 0) return;
    } else {
        int t = mbase >> 7;
        rowlim = NACT[t];
        if (rowlim <= 0) return;
    }
    bool wact = (wm * 32) < rowlim;

    float acc[2][4][4];
#pragma unroll
    for (int i = 0; i < 2; i++)
#pragma unroll
        for (int j = 0; j < 4; j++)
#pragma unroll
            for (int q = 0; q < 4; q++) acc[i][j][q] = 0.0f;

    // staging assignments
    int arow = tid >> 1, aks = (tid & 1) * 16;      // A: 16 elems/thread
    int brow = tid & 63, bks = (tid >> 6) * 8;      // B: 8 elems/thread
    const float* Asrc = A + (size_t)(mbase + arow) * K;
    const float* Wsrc = W + (size_t)(nbase + brow) * K;

    for (int kb = 0; kb < K; kb += 32) {
        __syncthreads();
        // ---- stage A (fp32 -> bf16 hi/lo pairs)
#pragma unroll
        for (int i = 0; i < 16; i += 2) {
            int k0 = kb + aks + i;
            float v0 = (k0     < K) ? Asrc[k0]     : 0.0f;
            float v1 = (k0 + 1 < K) ? Asrc[k0 + 1] : 0.0f;
            __nv_bfloat16 h0 = __float2bfloat16(v0);
            __nv_bfloat16 h1 = __float2bfloat16(v1);
            __nv_bfloat16 l0 = __float2bfloat16(v0 - __bfloat162float(h0));
            __nv_bfloat16 l1 = __float2bfloat16(v1 - __bfloat162float(h1));
            unsigned hp = (unsigned)__bfloat16_as_ushort(h0) |
                          ((unsigned)__bfloat16_as_ushort(h1) << 16);
            unsigned lp = (unsigned)__bfloat16_as_ushort(l0) |
                          ((unsigned)__bfloat16_as_ushort(l1) << 16);
            Ah[arow * 20 + (aks + i) / 2] = hp;
            Al[arow * 20 + (aks + i) / 2] = lp;
        }
        // ---- stage B (W rows)
#pragma unroll
        for (int i = 0; i < 8; i += 2) {
            int k0 = kb + bks + i;
            float v0 = (k0     < K) ? Wsrc[k0]     : 0.0f;
            float v1 = (k0 + 1 < K) ? Wsrc[k0 + 1] : 0.0f;
            __nv_bfloat16 h0 = __float2bfloat16(v0);
            __nv_bfloat16 h1 = __float2bfloat16(v1);
            __nv_bfloat16 l0 = __float2bfloat16(v0 - __bfloat162float(h0));
            __nv_bfloat16 l1 = __float2bfloat16(v1 - __bfloat162float(h1));
            unsigned hp = (unsigned)__bfloat16_as_ushort(h0) |
                          ((unsigned)__bfloat16_as_ushort(h1) << 16);
            unsigned lp = (unsigned)__bfloat16_as_ushort(l0) |
                          ((unsigned)__bfloat16_as_ushort(l1) << 16);
            Bh[brow * 20 + (bks + i) / 2] = hp;
            Bl[brow * 20 + (bks + i) / 2] = lp;
        }
        __syncthreads();

        if (!wact) continue;
        // ---- compute: 2 k16 steps per k-block
#pragma unroll
        for (int kt = 0; kt < 2; kt++) {
            int kp = kt * 8 + lc;
            unsigned ah[2][4], al[2][4];
#pragma unroll
            for (int mt = 0; mt < 2; mt++) {
                int rb = wm * 32 + mt * 16;
                ah[mt][0] = Ah[(rb + lr)     * 20 + kp];
                ah[mt][1] = Ah[(rb + 8 + lr) * 20 + kp];
                ah[mt][2] = Ah[(rb + lr)     * 20 + kp + 4];
                ah[mt][3] = Ah[(rb + 8 + lr) * 20 + kp + 4];
                al[mt][0] = Al[(rb + lr)     * 20 + kp];
                al[mt][1] = Al[(rb + 8 + lr) * 20 + kp];
                al[mt][2] = Al[(rb + lr)     * 20 + kp + 4];
                al[mt][3] = Al[(rb + 8 + lr) * 20 + kp + 4];
            }
#pragma unroll
            for (int nt = 0; nt < 4; nt++) {
                int nb = wn * 32 + nt * 8;
                unsigned bh0 = Bh[(nb + lr) * 20 + kp];
                unsigned bh1 = Bh[(nb + lr) * 20 + kp + 4];
                unsigned bl0 = Bl[(nb + lr) * 20 + kp];
                unsigned bl1 = Bl[(nb + lr) * 20 + kp + 4];
#pragma unroll
                for (int mt = 0; mt < 2; mt++) {
                    MMA_BF16(acc[mt][nt], ah[mt][0], ah[mt][1], ah[mt][2], ah[mt][3], bh0, bh1);
                    MMA_BF16(acc[mt][nt], ah[mt][0], ah[mt][1], ah[mt][2], ah[mt][3], bl0, bl1);
                    MMA_BF16(acc[mt][nt], al[mt][0], al[mt][1], al[mt][2], al[mt][3], bh0, bh1);
                }
            }
        }
    }

    // ---- store with bias (active rows only; mode-1 rank-permuted rows)
#pragma unroll
    for (int mt = 0; mt < 2; mt++) {
#pragma unroll
        for (int nt = 0; nt < 4; nt++) {
            int col = nbase + wn * 32 + nt * 8 + lc * 2;
            float bia0 = b1[col] + b2[col];
            float bia1 = b1[col + 1] + b2[col + 1];
#pragma unroll
            for (int h = 0; h < 2; h++) {
                int lrow = wm * 32 + mt * 16 + h * 8 + lr;
                if (lrow >= rowlim) continue;
                int m = mbase + lrow;
                int crow = (mode == 1) ? (((m & 255) << 7) + RANK[m >> 8]) : m;
                float* Cr = C + (size_t)crow * G4 + col;
                Cr[0] = acc[mt][nt][h * 2]     + bia0;
                Cr[1] = acc[mt][nt][h * 2 + 1] + bia1;
            }
        }
    }
}

// ---------------- grid-wide barrier -----------------------------------------
__device__ __forceinline__ void gsync(unsigned int& lg) {
    __syncthreads();
    if (threadIdx.x == 0) {
        __threadfence();
        unsigned int target = lg + 1;
        if (atomicAdd(&BAR_CNT, 1u) == (unsigned)(NB_RECUR - 1)) {
            atomicExch(&BAR_CNT, 0u);
            __threadfence();
            BAR_GEN = target;
        } else {
            while (BAR_GEN < target) __nanosleep(64);
        }
    }
    lg++;
    __syncthreads();
}

// ---------------- persistent recurrence kernel ------------------------------
struct RQ {
    const float* pre[2];
    const float* whh[2];
    float* ha[2];
    float* hb[2];
    float* outp[2];     // pre-offset by dir*512; nullptr = no output
    int rev[2];
};

template <int NC, int RPT>
__global__ void __launch_bounds__(256, 1) k_recur2(RQ p) {
    extern __shared__ float sm[];
    const int WS = NC * 4 + 4;           // padded wrow stride (floats)
    float* ws = sm;                      // [512][WS]
    float* hs = sm + 512 * WS;           // [64][128]  k-major h chunk

    int tid = threadIdx.x;
    const int bpd = (NC == 8) ? 64 : 128;     // blocks per direction
    int dir = blockIdx.x / bpd;
    int j0  = (blockIdx.x % bpd) * NC;

    const float* whh = p.whh[dir];
    const float* pre = p.pre[dir];
    float* ha = p.ha[dir];
    float* hb = p.hb[dir];
    float* outp = p.outp[dir];
    int rev = p.rev[dir];

    // one-time W tile load: ws[k][wl], wl = jj*4 + g, global wrow = g*512+j0+jj
    for (int idx = tid; idx < 512 * NC * 4; idx += 256) {
        int k  = idx & 511;
        int wl = idx >> 9;
        int jj = wl >> 2, g = wl & 3;
        ws[k * WS + wl] = whh[((size_t)(g * 512 + j0 + jj)) * 512 + k];
    }

    int tx = tid & (NC - 1);
    int ty = tid >> ((NC == 8) ? 3 : 2);
    int jg = j0 + tx;
    int r0 = ty * RPT;
    int rstage = tid & 127;
    int half = tid >> 7;

    float hreg[RPT], creg[RPT];
#pragma unroll
    for (int i = 0; i < RPT; i++) { hreg[i] = 1.0f; creg[i] = 1.0f; }

    unsigned int lg = 0;

    for (int s = 0; s < SSZ; s++) {
        int tt = rev ? (SSZ - 1 - s) : s;
        int nact = NACT[tt];
        const float* hin = (s & 1) ? hb : ha;
        float* hout      = (s & 1) ? ha : hb;

        float acc[RPT][4];
#pragma unroll
        for (int i = 0; i < RPT; i++) {
            acc[i][0] = 0.f; acc[i][1] = 0.f; acc[i][2] = 0.f; acc[i][3] = 0.f;
        }
        bool act_gemm = (r0 < nact);

        for (int kb = 0; kb < HSZ; kb += 64) {
            __syncthreads();            // hs free from previous chunk
            if (rstage < nact) {
                const float4* src = (const float4*)(hin + (size_t)rstage * HSZ + kb);
#pragma unroll
                for (int q = 0; q < 8; q++) {
                    int qi = half * 8 + q;
                    float4 v = src[qi];
                    hs[(qi * 4 + 0) * 128 + rstage] = v.x;
                    hs[(qi * 4 + 1) * 128 + rstage] = v.y;
                    hs[(qi * 4 + 2) * 128 + rstage] = v.z;
                    hs[(qi * 4 + 3) * 128 + rstage] = v.w;
                }
            }
            __syncthreads();
            if (act_gemm) {
#pragma unroll 8
                for (int kk = 0; kk < 64; kk++) {
                    float4 bv = *(const float4*)(ws + (kb + kk) * WS + tx * 4);
                    if (RPT == 4) {
                        float4 av = *(const float4*)(hs + kk * 128 + r0);
                        acc[0][0] += av.x * bv.x; acc[0][1] += av.x * bv.y;
                        acc[0][2] += av.x * bv.z; acc[0][3] += av.x * bv.w;
                        acc[1][0] += av.y * bv.x; acc[1][1] += av.y * bv.y;
                        acc[1][2] += av.y * bv.z; acc[1][3] += av.y * bv.w;
                        acc[2][0] += av.z * bv.x; acc[2][1] += av.z * bv.y;
                        acc[2][2] += av.z * bv.z; acc[2][3] += av.z * bv.w;
                        acc[3][0] += av.w * bv.x; acc[3][1] += av.w * bv.y;
                        acc[3][2] += av.w * bv.z; acc[3][3] += av.w * bv.w;
                    } else {
                        float2 av = *(const float2*)(hs + kk * 128 + r0);
                        acc[0][0] += av.x * bv.x; acc[0][1] += av.x * bv.y;
                        acc[0][2] += av.x * bv.z; acc[0][3] += av.x * bv.w;
                        acc[1][0] += av.y * bv.x; acc[1][1] += av.y * bv.y;
                        acc[1][2] += av.y * bv.z; acc[1][3] += av.y * bv.w;
                    }
                }
            }
        }

        // gates: acc[i][g] are the 4 gates of cell (r0+i, jg); c/h in registers
#pragma unroll
        for (int i = 0; i < RPT; i++) {
            int r = r0 + i;
            if (r < nact) {
                const float* pb = pre + ((size_t)tt * BSZ + r) * G4 + jg;
                float zi = acc[i][0] + pb[0];
                float zf = acc[i][1] + pb[512];
                float zg = acc[i][2] + pb[1024];
                float zo = acc[i][3] + pb[1536];
                float cn = sigm(zf) * creg[i] + sigm(zi) * tanhf(zg);
                creg[i] = cn;
                hreg[i] = sigm(zo) * tanhf(cn);
            }
            hout[(size_t)r * HSZ + jg] = hreg[i];
            if (outp) outp[((size_t)tt * BSZ + r) * (2 * HSZ) + jg] = hreg[i];
        }
        gsync(lg);
    }
}

// ---------------- final FC head: out = (h@fc1^T + b1) @ fc^T + b ------------
__global__ void k_fc(const float* __restrict__ h,
                     const float* __restrict__ fc1w, const float* __restrict__ fc1b,
                     const float* __restrict__ fcw,  const float* __restrict__ fcb,
                     float* __restrict__ out)
{
    __shared__ float tmp[HSZ];
    __shared__ float red[2][256];
    int b = blockIdx.x, tid = threadIdx.x;
    const float* hb = h + (size_t)RANK[b] * HSZ;   // rank-permuted h rows

    for (int j = tid; j < HSZ; j += 256) {
        const float* w = fc1w + (size_t)j * HSZ;
        float s0 = 0.f, s1 = 0.f, s2 = 0.f, s3 = 0.f;
        for (int k = 0; k < HSZ; k += 4) {
            s0 += hb[k] * w[k];         s1 += hb[k + 1] * w[k + 1];
            s2 += hb[k + 2] * w[k + 2]; s3 += hb[k + 3] * w[k + 3];
        }
        tmp[j] = s0 + s1 + s2 + s3 + fc1b[j];
    }
    __syncthreads();
    float p0 = 0.f, p1 = 0.f;
    for (int k = tid; k < HSZ; k += 256) {
        p0 += tmp[k] * fcw[k];
        p1 += tmp[k] * fcw[HSZ + k];
    }
    red[0][tid] = p0; red[1][tid] = p1;
    __syncthreads();
    for (int off = 128; off > 0; off >>= 1) {
        if (tid < off) {
            red[0][tid] += red[0][tid + off];
            red[1][tid] += red[1][tid + off];
        }
        __syncthreads();
    }
    if (tid == 0) {
        out[b * 2 + 0] = red[0][0] + fcb[0];
        out[b * 2 + 1] = red[1][0] + fcb[1];
    }
}

// ---------------- host launch sequence --------------------------------------
template <typename T>
static float* sym_addr(T& sym) {
    void* p = nullptr;
    cudaGetSymbolAddress(&p, sym);
    return (float*)p;
}

extern "C" void kernel_launch(void* const* d_in, const int* in_sizes, int n_in,
                              void* d_out, int out_size)
{
    const float* x          = (const float*)d_in[0];
    const float* w_ih_l0_f  = (const float*)d_in[1];
    const float* w_hh_l0_f  = (const float*)d_in[2];
    const float* b_ih_l0_f  = (const float*)d_in[3];
    const float* b_hh_l0_f  = (const float*)d_in[4];
    const float* w_ih_l0_r  = (const float*)d_in[5];
    const float* w_hh_l0_r  = (const float*)d_in[6];
    const float* b_ih_l0_r  = (const float*)d_in[7];
    const float* b_hh_l0_r  = (const float*)d_in[8];
    // d_in[9..12] = layer-1 forward (dead code in reference: only hT_r is used)
    const float* w_ih_l1_r  = (const float*)d_in[13];
    const float* w_hh_l1_r  = (const float*)d_in[14];
    const float* b_ih_l1_r  = (const float*)d_in[15];
    const float* b_hh_l1_r  = (const float*)d_in[16];
    const float* fc1_w      = (const float*)d_in[17];
    const float* fc1_b      = (const float*)d_in[18];
    const float* fc_w       = (const float*)d_in[19];
    const float* fc_b       = (const float*)d_in[20];
    float* out = (float*)d_out;

    float* pre0f = sym_addr(PRE0F);
    float* pre0r = sym_addr(PRE0R);
    float* pre1  = pre0f;               // alias: PRE0F dead after layer-0 recurrence
    float* out0  = sym_addr(OUT0);
    float* hbuf  = sym_addr(HBUF);
    const int slab = BSZ * HSZ;
    const int M = BSZ * SSZ;            // 32768

    // dynamic-smem opt-in for the persistent recurrence kernels
    const int SM8 = (512 * (8 * 4 + 4) + 64 * 128) * 4;   // 106496 B
    const int SM4 = (512 * (4 * 4 + 4) + 64 * 128) * 4;   //  73728 B
    cudaFuncSetAttribute(k_recur2<8, 4>, cudaFuncAttributeMaxDynamicSharedMemorySize, SM8);
    cudaFuncSetAttribute(k_recur2<4, 2>, cudaFuncAttributeMaxDynamicSharedMemorySize, SM4);

    // 1) init + rank/NACT prep                                   (launch 1,2)
    k_init<<<768, 256>>>(x);
    k_prep<<<1, BSZ>>>();

    // 2) layer-0 input projections, tensor-core hi/lo bf16       (launch 3,4)
    dim3 gtc(32, 256);    // N/64 x M/128
    k_gemm_tc<<<gtc, 256>>>(x, M, ESZ, w_ih_l0_f, b_ih_l0_f, b_hh_l0_f, pre0f, 1);
    k_gemm_tc<<<gtc, 256>>>(x, M, ESZ, w_ih_l0_r, b_ih_l0_r, b_hh_l0_r, pre0r, 1);

    // pad launch so ncu (-s 5 -c 1) profiles k_recur2<8,4> next  (launch 5)
    k_reset<<<1, 1>>>();

    // 3) layer-0 recurrence: both directions, persistent          (launch 6)
    RQ rq0;
    rq0.pre[0] = pre0f; rq0.whh[0] = w_hh_l0_f;
    rq0.ha[0] = hbuf + 0 * slab; rq0.hb[0] = hbuf + 1 * slab;
    rq0.outp[0] = out0;           rq0.rev[0] = 0;
    rq0.pre[1] = pre0r; rq0.whh[1] = w_hh_l0_r;
    rq0.ha[1] = hbuf + 3 * slab; rq0.hb[1] = hbuf + 4 * slab;
    rq0.outp[1] = out0 + HSZ;     rq0.rev[1] = 1;
    k_recur2<8, 4><<<NB_RECUR, 256, SM8>>>(rq0);

    // 4) layer-1 (reverse only) projection                        (launch 7)
    k_gemm_tc<<<gtc, 256>>>(out0, M, 2 * HSZ, w_ih_l1_r, b_ih_l1_r, b_hh_l1_r, pre1, 2);

    // 5) layer-1 reverse recurrence                               (launch 8,9)
    k_reset<<<1, 1>>>();
    RQ rq1;
    rq1.pre[0] = pre1; rq1.whh[0] = w_hh_l1_r;
    rq1.ha[0] = hbuf + 6 * slab; rq1.hb[0] = hbuf + 7 * slab;
    rq1.outp[0] = nullptr;        rq1.rev[0] = 1;
    rq1.pre[1] = nullptr; rq1.whh[1] = nullptr;
    rq1.ha[1] = nullptr; rq1.hb[1] = nullptr;
    rq1.outp[1] = nullptr;        rq1.rev[1] = 0;
    k_recur2<4, 2><<<NB_RECUR, 256, SM4>>>(rq1);

    // 6) FC head; final h (s=255 -> hout = ha = buf 6), rank-indirected (launch 10)
    k_fc<<<BSZ, 256>>>(hbuf + 6 * slab, fc1_w, fc1_b, fc_w, fc_b, out);
}

// round 13
// speedup vs baseline: 1.4167x; 1.4167x over previous
#include <cuda_runtime.h>
#include <math.h>

// Problem constants
#define BSZ 128
#define SSZ 256
#define ESZ 300
#define HSZ 512
#define G4  2048           // 4*H
#define NB_RECUR 128       // persistent kernel grid (<= 148 SMs -> co-resident wave 1)

// ---------------- scratch (static device memory; no runtime allocation) -----
// PRE1 aliases PRE0F (l0-fwd pre fully consumed before l1 projection runs).
// All [t][r] tensors are stored in RANK-permuted batch order (r = rank).
__device__ float PRE0F[SSZ * BSZ * G4];          // [t][r][4H] l0 fwd  (later: l1 rev)
__device__ float PRE0R[SSZ * BSZ * G4];          // [t][r][4H] l0 rev
__device__ float OUT0 [SSZ * BSZ * 2 * HSZ];     // [t][r][2H] concat(fwd,rev)
__device__ float HBUF [9][BSZ * HSZ];            // h double-buffers (rank-permuted rows)
__device__ int   LEN[BSZ];
__device__ int   RANK[BSZ];                      // original b -> rank (desc by length)
__device__ int   NACT[SSZ];                      // #rows with len > t
__device__ unsigned int BAR_CNT;
__device__ volatile unsigned int BAR_GEN;

__device__ __forceinline__ float sigm(float x) { return 1.0f / (1.0f + expf(-x)); }

// ---------------- init: lengths, ones-init h buffers, barrier reset ---------
__global__ void k_init(const float* __restrict__ x) {
    int tid = blockIdx.x * blockDim.x + threadIdx.x;
    const int slab = BSZ * HSZ;                   // 65536
    if (tid < 3 * slab) {                         // ones-init h bufs 0, 3, 6
        int w = tid / slab, i = tid - w * slab;
        HBUF[w * 3][i] = 1.0f;
    }
    if (tid < BSZ) {
        int v = (int)x[((size_t)tid * SSZ + (SSZ - 1)) * ESZ];  // x[b, S-1, 0]
        LEN[tid] = v < SSZ ? v : SSZ;
    }
    if (tid == 0) { BAR_CNT = 0; BAR_GEN = 0; }
}

__global__ void k_reset() { BAR_CNT = 0; BAR_GEN = 0; }

// ---------------- prep: rank permutation (desc length, stable) + NACT -------
__global__ void k_prep() {
    __shared__ int sl[BSZ];
    int b = threadIdx.x;            // 128 threads
    sl[b] = LEN[b];
    __syncthreads();
    int mylen = sl[b];
    int rk = 0;
    for (int o = 0; o < BSZ; o++) {
        int lo = sl[o];
        rk += (lo > mylen) || (lo == mylen && o < b);
    }
    RANK[b] = rk;
    for (int t = b; t < SSZ; t += BSZ) {
        int c = 0;
        for (int o = 0; o < BSZ; o++) c += (sl[o] > t);
        NACT[t] = c;
    }
}

// ---------------- big NT-GEMM: C = A[M,K] * W[2048,K]^T + b1 + b2 -----------
// 128x128 block tile, 8x8 microtile, KC=8.  (fp32 — proven 650us @ K=300)
// mode 1: layer-0 projection. A rows = b*S+t. Output row = t*128 + RANK[b].
//         Row-activity: rowlim = LEN[b]-t0 (tile spans one b).
// mode 2: layer-1 projection. A rows = t*128 + r. Output row = m.
//         Row-activity: rowlim = NACT[t] (tile = one t).
__global__ void __launch_bounds__(256, 1) k_gemm(
    const float* __restrict__ A, int M, int K,
    const float* __restrict__ W,
    const float* __restrict__ b1, const float* __restrict__ b2,
    float* __restrict__ C, int mode)
{
    __shared__ float As[8][128];
    __shared__ float Bs[8][128];

    int tid = threadIdx.x;
    int ty = tid >> 4, tx = tid & 15;
    int mbase = blockIdx.y * 128;
    int nbase = blockIdx.x * 128;

    int rowlim = 128;
    if (mode == 1) {
        int b = mbase >> 8, t0 = mbase & 255;
        rowlim = LEN[b] - t0;
        if (rowlim > 128) rowlim = 128;
        if (rowlim <= 0) return;
    } else if (mode == 2) {
        int t = mbase >> 7;
        rowlim = NACT[t];
        if (rowlim <= 0) return;
    }
    bool act = (ty * 8) < rowlim;

    float acc[8][8];
#pragma unroll
    for (int i = 0; i < 8; i++)
#pragma unroll
        for (int j = 0; j < 8; j++) acc[i][j] = 0.0f;

    int lrow = tid >> 1;            // 0..127
    int lk   = (tid & 1) * 4;       // 0 or 4
    const float* Arow = A + (size_t)(mbase + lrow) * K;
    const float* Wrow = W + (size_t)(nbase + lrow) * K;

    for (int kb = 0; kb < K; kb += 8) {
        float av[4], wv[4];
        if (kb + lk + 3 < K) {
            float4 t = *(const float4*)(Arow + kb + lk);
            av[0] = t.x; av[1] = t.y; av[2] = t.z; av[3] = t.w;
            float4 u = *(const float4*)(Wrow + kb + lk);
            wv[0] = u.x; wv[1] = u.y; wv[2] = u.z; wv[3] = u.w;
        } else {
#pragma unroll
            for (int i = 0; i < 4; i++) {
                int k = kb + lk + i;
                av[i] = (k < K) ? Arow[k] : 0.0f;
                wv[i] = (k < K) ? Wrow[k] : 0.0f;
            }
        }
        __syncthreads();
#pragma unroll
        for (int i = 0; i < 4; i++) {
            As[lk + i][lrow] = av[i];
            Bs[lk + i][lrow] = wv[i];
        }
        __syncthreads();
        if (act) {
#pragma unroll
            for (int kk = 0; kk < 8; kk++) {
                float a[8], b[8];
                *(float4*)&a[0] = *(const float4*)&As[kk][ty * 8];
                *(float4*)&a[4] = *(const float4*)&As[kk][ty * 8 + 4];
                *(float4*)&b[0] = *(const float4*)&Bs[kk][tx * 8];
                *(float4*)&b[4] = *(const float4*)&Bs[kk][tx * 8 + 4];
#pragma unroll
                for (int i = 0; i < 8; i++)
#pragma unroll
                    for (int j = 0; j < 8; j++) acc[i][j] += a[i] * b[j];
            }
        }
    }

    // store with bias (active rows only)
#pragma unroll
    for (int i = 0; i < 8; i++) {
        int lr = ty * 8 + i;
        if (lr >= rowlim) continue;
        int m = mbase + lr;
        int crow = (mode == 1) ? (((m & 255) << 7) + RANK[m >> 8]) : m;
        float* Cr = C + (size_t)crow * G4 + nbase + tx * 8;
        const float* p1 = b1 + nbase + tx * 8;
        const float* p2 = b2 + nbase + tx * 8;
#pragma unroll
        for (int j = 0; j < 8; j++) Cr[j] = acc[i][j] + p1[j] + p2[j];
    }
}

// ---------------- grid-wide barrier -----------------------------------------
__device__ __forceinline__ void gsync(unsigned int& lg) {
    __syncthreads();
    if (threadIdx.x == 0) {
        __threadfence();
        unsigned int target = lg + 1;
        if (atomicAdd(&BAR_CNT, 1u) == (unsigned)(NB_RECUR - 1)) {
            atomicExch(&BAR_CNT, 0u);
            __threadfence();
            BAR_GEN = target;
        } else {
            while (BAR_GEN < target) __nanosleep(64);
        }
    }
    lg++;
    __syncthreads();
}

// ---------------- persistent recurrence kernel ------------------------------
// Block = (direction, NC hidden cols). W_hh tile resident in smem for all 256
// steps; each thread's accumulators are the 4 gates of RPT (row, col) cells ->
// gate math register-local; c and own-h live in registers for the whole scan.
// Software-pipelined: next h-chunk's LDGs are issued during current chunk's
// compute; pre (gate inputs) prefetched at step start. 1 grid sync per step.
struct RQ {
    const float* pre[2];
    const float* whh[2];
    float* ha[2];
    float* hb[2];
    float* outp[2];     // pre-offset by dir*512; nullptr = no output
    int rev[2];
};

template <int NC, int RPT>
__global__ void __launch_bounds__(256, 1) k_recur2(RQ p) {
    extern __shared__ float sm[];
    const int WS = NC * 4 + 4;           // padded wrow stride (floats)
    float* ws = sm;                      // [512][WS]
    float* hs = sm + 512 * WS;           // [64][128]  k-major h chunk

    int tid = threadIdx.x;
    const int bpd = (NC == 8) ? 64 : 128;     // blocks per direction
    int dir = blockIdx.x / bpd;
    int j0  = (blockIdx.x % bpd) * NC;

    const float* whh = p.whh[dir];
    const float* pre = p.pre[dir];
    float* ha = p.ha[dir];
    float* hb = p.hb[dir];
    float* outp = p.outp[dir];
    int rev = p.rev[dir];

    // one-time W tile load: ws[k][wl], wl = jj*4 + g, global wrow = g*512+j0+jj
    for (int idx = tid; idx < 512 * NC * 4; idx += 256) {
        int k  = idx & 511;
        int wl = idx >> 9;
        int jj = wl >> 2, g = wl & 3;
        ws[k * WS + wl] = whh[((size_t)(g * 512 + j0 + jj)) * 512 + k];
    }

    int tx = tid & (NC - 1);
    int ty = tid >> ((NC == 8) ? 3 : 2);
    int jg = j0 + tx;
    int r0 = ty * RPT;
    int rstage = tid & 127;
    int half = tid >> 7;

    float hreg[RPT], creg[RPT];
#pragma unroll
    for (int i = 0; i < RPT; i++) { hreg[i] = 1.0f; creg[i] = 1.0f; }

    unsigned int lg = 0;

    for (int s = 0; s < SSZ; s++) {
        int tt = rev ? (SSZ - 1 - s) : s;
        int nact = NACT[tt];
        const float* hin = (s & 1) ? hb : ha;
        float* hout      = (s & 1) ? ha : hb;
        bool do_stage = (rstage < nact);
        bool act_gemm = (r0 < nact);

        // ---- prefetch gate pre-activations for this step (consumed after GEMM)
        float pz[RPT][4];
#pragma unroll
        for (int i = 0; i < RPT; i++) {
            if (r0 + i < nact) {
                const float* pb = pre + ((size_t)tt * BSZ + (r0 + i)) * G4 + jg;
                pz[i][0] = pb[0];
                pz[i][1] = pb[512];
                pz[i][2] = pb[1024];
                pz[i][3] = pb[1536];
            }
        }

        float acc[RPT][4];
#pragma unroll
        for (int i = 0; i < RPT; i++) {
            acc[i][0] = 0.f; acc[i][1] = 0.f; acc[i][2] = 0.f; acc[i][3] = 0.f;
        }

        // ---- prefetch chunk 0 of h into registers
        float4 stg[8];
        if (do_stage) {
            const float4* src = (const float4*)(hin + (size_t)rstage * HSZ);
#pragma unroll
            for (int q = 0; q < 8; q++) stg[q] = src[half * 8 + q];
        }

        for (int kb = 0; kb < HSZ; kb += 64) {
            __syncthreads();            // hs free (prev chunk's compute done)
            if (do_stage) {
#pragma unroll
                for (int q = 0; q < 8; q++) {
                    int qi = half * 8 + q;
                    hs[(qi * 4 + 0) * 128 + rstage] = stg[q].x;
                    hs[(qi * 4 + 1) * 128 + rstage] = stg[q].y;
                    hs[(qi * 4 + 2) * 128 + rstage] = stg[q].z;
                    hs[(qi * 4 + 3) * 128 + rstage] = stg[q].w;
                }
            }
            __syncthreads();            // hs ready
            // issue next chunk's LDGs now; they complete during compute below
            if (kb + 64 < HSZ && do_stage) {
                const float4* src = (const float4*)(hin + (size_t)rstage * HSZ + kb + 64);
#pragma unroll
                for (int q = 0; q < 8; q++) stg[q] = src[half * 8 + q];
            }
            if (act_gemm) {
#pragma unroll 16
                for (int kk = 0; kk < 64; kk++) {
                    float4 bv = *(const float4*)(ws + (kb + kk) * WS + tx * 4);
                    if (RPT == 4) {
                        float4 av = *(const float4*)(hs + kk * 128 + r0);
                        acc[0][0] += av.x * bv.x; acc[0][1] += av.x * bv.y;
                        acc[0][2] += av.x * bv.z; acc[0][3] += av.x * bv.w;
                        acc[1][0] += av.y * bv.x; acc[1][1] += av.y * bv.y;
                        acc[1][2] += av.y * bv.z; acc[1][3] += av.y * bv.w;
                        acc[2][0] += av.z * bv.x; acc[2][1] += av.z * bv.y;
                        acc[2][2] += av.z * bv.z; acc[2][3] += av.z * bv.w;
                        acc[3][0] += av.w * bv.x; acc[3][1] += av.w * bv.y;
                        acc[3][2] += av.w * bv.z; acc[3][3] += av.w * bv.w;
                    } else {
                        float2 av = *(const float2*)(hs + kk * 128 + r0);
                        acc[0][0] += av.x * bv.x; acc[0][1] += av.x * bv.y;
                        acc[0][2] += av.x * bv.z; acc[0][3] += av.x * bv.w;
                        acc[1][0] += av.y * bv.x; acc[1][1] += av.y * bv.y;
                        acc[1][2] += av.y * bv.z; acc[1][3] += av.y * bv.w;
                    }
                }
            }
        }

        // gates: acc[i][g] are the 4 gates of cell (r0+i, jg); c/h in registers
#pragma unroll
        for (int i = 0; i < RPT; i++) {
            int r = r0 + i;
            if (r < nact) {
                float zi = acc[i][0] + pz[i][0];
                float zf = acc[i][1] + pz[i][1];
                float zg = acc[i][2] + pz[i][2];
                float zo = acc[i][3] + pz[i][3];
                float cn = sigm(zf) * creg[i] + sigm(zi) * tanhf(zg);
                creg[i] = cn;
                hreg[i] = sigm(zo) * tanhf(cn);
            }
            hout[(size_t)r * HSZ + jg] = hreg[i];
            if (outp) outp[((size_t)tt * BSZ + r) * (2 * HSZ) + jg] = hreg[i];
        }
        gsync(lg);
    }
}

// ---------------- final FC head: out = (h@fc1^T + b1) @ fc^T + b ------------
__global__ void k_fc(const float* __restrict__ h,
                     const float* __restrict__ fc1w, const float* __restrict__ fc1b,
                     const float* __restrict__ fcw,  const float* __restrict__ fcb,
                     float* __restrict__ out)
{
    __shared__ float tmp[HSZ];
    __shared__ float red[2][256];
    int b = blockIdx.x, tid = threadIdx.x;
    const float* hb = h + (size_t)RANK[b] * HSZ;   // rank-permuted h rows

    for (int j = tid; j < HSZ; j += 256) {
        const float* w = fc1w + (size_t)j * HSZ;
        float s0 = 0.f, s1 = 0.f, s2 = 0.f, s3 = 0.f;
        for (int k = 0; k < HSZ; k += 4) {
            s0 += hb[k] * w[k];         s1 += hb[k + 1] * w[k + 1];
            s2 += hb[k + 2] * w[k + 2]; s3 += hb[k + 3] * w[k + 3];
        }
        tmp[j] = s0 + s1 + s2 + s3 + fc1b[j];
    }
    __syncthreads();
    float p0 = 0.f, p1 = 0.f;
    for (int k = tid; k < HSZ; k += 256) {
        p0 += tmp[k] * fcw[k];
        p1 += tmp[k] * fcw[HSZ + k];
    }
    red[0][tid] = p0; red[1][tid] = p1;
    __syncthreads();
    for (int off = 128; off > 0; off >>= 1) {
        if (tid < off) {
            red[0][tid] += red[0][tid + off];
            red[1][tid] += red[1][tid + off];
        }
        __syncthreads();
    }
    if (tid == 0) {
        out[b * 2 + 0] = red[0][0] + fcb[0];
        out[b * 2 + 1] = red[1][0] + fcb[1];
    }
}

// ---------------- host launch sequence --------------------------------------
template <typename T>
static float* sym_addr(T& sym) {
    void* p = nullptr;
    cudaGetSymbolAddress(&p, sym);
    return (float*)p;
}

extern "C" void kernel_launch(void* const* d_in, const int* in_sizes, int n_in,
                              void* d_out, int out_size)
{
    const float* x          = (const float*)d_in[0];
    const float* w_ih_l0_f  = (const float*)d_in[1];
    const float* w_hh_l0_f  = (const float*)d_in[2];
    const float* b_ih_l0_f  = (const float*)d_in[3];
    const float* b_hh_l0_f  = (const float*)d_in[4];
    const float* w_ih_l0_r  = (const float*)d_in[5];
    const float* w_hh_l0_r  = (const float*)d_in[6];
    const float* b_ih_l0_r  = (const float*)d_in[7];
    const float* b_hh_l0_r  = (const float*)d_in[8];
    // d_in[9..12] = layer-1 forward (dead code in reference: only hT_r is used)
    const float* w_ih_l1_r  = (const float*)d_in[13];
    const float* w_hh_l1_r  = (const float*)d_in[14];
    const float* b_ih_l1_r  = (const float*)d_in[15];
    const float* b_hh_l1_r  = (const float*)d_in[16];
    const float* fc1_w      = (const float*)d_in[17];
    const float* fc1_b      = (const float*)d_in[18];
    const float* fc_w       = (const float*)d_in[19];
    const float* fc_b       = (const float*)d_in[20];
    float* out = (float*)d_out;

    float* pre0f = sym_addr(PRE0F);
    float* pre0r = sym_addr(PRE0R);
    float* pre1  = pre0f;               // alias: PRE0F dead after layer-0 recurrence
    float* out0  = sym_addr(OUT0);
    float* hbuf  = sym_addr(HBUF);
    const int slab = BSZ * HSZ;
    const int M = BSZ * SSZ;            // 32768

    // dynamic-smem opt-in for the persistent recurrence kernels
    const int SM8 = (512 * (8 * 4 + 4) + 64 * 128) * 4;   // 106496 B
    const int SM4 = (512 * (4 * 4 + 4) + 64 * 128) * 4;   //  73728 B
    cudaFuncSetAttribute(k_recur2<8, 4>, cudaFuncAttributeMaxDynamicSharedMemorySize, SM8);
    cudaFuncSetAttribute(k_recur2<4, 2>, cudaFuncAttributeMaxDynamicSharedMemorySize, SM4);

    // 1) init + rank/NACT prep                                   (launch 1,2)
    k_init<<<768, 256>>>(x);
    k_prep<<<1, BSZ>>>();

    // 2) layer-0 input projections, fp32 SGEMM                   (launch 3,4)
    dim3 gg(16, 256);
    k_gemm<<<gg, 256>>>(x, M, ESZ, w_ih_l0_f, b_ih_l0_f, b_hh_l0_f, pre0f, 1);
    k_gemm<<<gg, 256>>>(x, M, ESZ, w_ih_l0_r, b_ih_l0_r, b_hh_l0_r, pre0r, 1);

    // pad launch so ncu (-s 5 -c 1) lands on k_recur2<8,4>       (launch 5)
    k_reset<<<1, 1>>>();

    // 3) layer-0 recurrence: both directions, persistent          (launch 6)
    RQ rq0;
    rq0.pre[0] = pre0f; rq0.whh[0] = w_hh_l0_f;
    rq0.ha[0] = hbuf + 0 * slab; rq0.hb[0] = hbuf + 1 * slab;
    rq0.outp[0] = out0;           rq0.rev[0] = 0;
    rq0.pre[1] = pre0r; rq0.whh[1] = w_hh_l0_r;
    rq0.ha[1] = hbuf + 3 * slab; rq0.hb[1] = hbuf + 4 * slab;
    rq0.outp[1] = out0 + HSZ;     rq0.rev[1] = 1;
    k_recur2<8, 4><<<NB_RECUR, 256, SM8>>>(rq0);

    // 4) layer-1 (reverse only) projection                        (launch 7)
    k_gemm<<<gg, 256>>>(out0, M, 2 * HSZ, w_ih_l1_r, b_ih_l1_r, b_hh_l1_r, pre1, 2);

    // 5) layer-1 reverse recurrence                               (launch 8,9)
    k_reset<<<1, 1>>>();
    RQ rq1;
    rq1.pre[0] = pre1; rq1.whh[0] = w_hh_l1_r;
    rq1.ha[0] = hbuf + 6 * slab; rq1.hb[0] = hbuf + 7 * slab;
    rq1.outp[0] = nullptr;        rq1.rev[0] = 1;
    rq1.pre[1] = nullptr; rq1.whh[1] = nullptr;
    rq1.ha[1] = nullptr; rq1.hb[1] = nullptr;
    rq1.outp[1] = nullptr;        rq1.rev[1] = 0;
    k_recur2<4, 2><<<NB_RECUR, 256, SM4>>>(rq1);

    // 6) FC head; final h (s=255 -> hout = ha = buf 6), rank-indirected (launch 10)
    k_fc<<<BSZ, 256>>>(hbuf + 6 * slab, fc1_w, fc1_b, fc_w, fc_b, out);
}

// round 14
// speedup vs baseline: 1.7919x; 1.2648x over previous
#include <cuda_runtime.h>
#include <cuda_bf16.h>
#include <math.h>

// Problem constants
#define BSZ 128
#define SSZ 256
#define ESZ 300
#define HSZ 512
#define G4  2048
#define NB_RECUR 128       // persistent grid: 1 block/SM, co-resident wave 1

// ---------------- scratch (static device memory) -----------------------------
__device__ float PRE0F[SSZ * BSZ * G4];          // [t][r][4H] l0 fwd (aliased: l1 rev)
__device__ float PRE0R[SSZ * BSZ * G4];          // [t][r][4H] l0 rev
__device__ float OUT0 [SSZ * BSZ * 2 * HSZ];     // [t][r][2H] fp32 concat(fwd,rev)
// h exchange planes (bf16): slot*4 + {A_hi, A_lo, B_hi, B_lo}; slots: l0f,l0r,l1r
__device__ __nv_bfloat16 HP[12][BSZ * HSZ];
__device__ float HFIN[BSZ * HSZ];                // fp32 final h of l1 (rank rows)
__device__ int   LEN[BSZ];
__device__ int   RANK[BSZ];
__device__ int   NACT[SSZ];
__device__ unsigned int BAR_CNT;
__device__ volatile unsigned int BAR_GEN;

__device__ __forceinline__ float sigm(float x) { return 1.0f / (1.0f + expf(-x)); }

__device__ __forceinline__ unsigned pack_bf16(float x, float y) {
    __nv_bfloat16 bx = __float2bfloat16(x), by = __float2bfloat16(y);
    return (unsigned)__bfloat16_as_ushort(bx) | ((unsigned)__bfloat16_as_ushort(by) << 16);
}

// ---------------- init ------------------------------------------------------
__global__ void k_init(const float* __restrict__ x) {
    int tid = blockIdx.x * blockDim.x + threadIdx.x;
    const int slab = BSZ * HSZ;
    if (tid < 3 * slab) {                 // h bufA planes: hi=1.0, lo=0
        int w = tid / slab, i = tid - w * slab;
        HP[w * 4 + 0][i] = __float2bfloat16(1.0f);
        HP[w * 4 + 1][i] = __float2bfloat16(0.0f);
    }
    if (tid < BSZ) {
        int v = (int)x[((size_t)tid * SSZ + (SSZ - 1)) * ESZ];
        LEN[tid] = v < SSZ ? v : SSZ;
    }
    if (tid == 0) { BAR_CNT = 0; BAR_GEN = 0; }
}

__global__ void k_reset() { BAR_CNT = 0; BAR_GEN = 0; }

// ---------------- prep: rank permutation + NACT ------------------------------
__global__ void k_prep() {
    __shared__ int sl[BSZ];
    int b = threadIdx.x;
    sl[b] = LEN[b];
    __syncthreads();
    int mylen = sl[b];
    int rk = 0;
    for (int o = 0; o < BSZ; o++) {
        int lo = sl[o];
        rk += (lo > mylen) || (lo == mylen && o < b);
    }
    RANK[b] = rk;
    for (int t = b; t < SSZ; t += BSZ) {
        int c = 0;
        for (int o = 0; o < BSZ; o++) c += (sl[o] > t);
        NACT[t] = c;
    }
}

// ---------------- fp32 NT-GEMM (input projections; proven) ------------------
__global__ void __launch_bounds__(256, 1) k_gemm(
    const float* __restrict__ A, int M, int K,
    const float* __restrict__ W,
    const float* __restrict__ b1, const float* __restrict__ b2,
    float* __restrict__ C, int mode)
{
    __shared__ float As[8][128];
    __shared__ float Bs[8][128];

    int tid = threadIdx.x;
    int ty = tid >> 4, tx = tid & 15;
    int mbase = blockIdx.y * 128;
    int nbase = blockIdx.x * 128;

    int rowlim = 128;
    if (mode == 1) {
        int b = mbase >> 8, t0 = mbase & 255;
        rowlim = LEN[b] - t0;
        if (rowlim > 128) rowlim = 128;
        if (rowlim <= 0) return;
    } else if (mode == 2) {
        int t = mbase >> 7;
        rowlim = NACT[t];
        if (rowlim <= 0) return;
    }
    bool act = (ty * 8) < rowlim;

    float acc[8][8];
#pragma unroll
    for (int i = 0; i < 8; i++)
#pragma unroll
        for (int j = 0; j < 8; j++) acc[i][j] = 0.0f;

    int lrow = tid >> 1;
    int lk   = (tid & 1) * 4;
    const float* Arow = A + (size_t)(mbase + lrow) * K;
    const float* Wrow = W + (size_t)(nbase + lrow) * K;

    for (int kb = 0; kb < K; kb += 8) {
        float av[4], wv[4];
        if (kb + lk + 3 < K) {
            float4 t = *(const float4*)(Arow + kb + lk);
            av[0] = t.x; av[1] = t.y; av[2] = t.z; av[3] = t.w;
            float4 u = *(const float4*)(Wrow + kb + lk);
            wv[0] = u.x; wv[1] = u.y; wv[2] = u.z; wv[3] = u.w;
        } else {
#pragma unroll
            for (int i = 0; i < 4; i++) {
                int k = kb + lk + i;
                av[i] = (k < K) ? Arow[k] : 0.0f;
                wv[i] = (k < K) ? Wrow[k] : 0.0f;
            }
        }
        __syncthreads();
#pragma unroll
        for (int i = 0; i < 4; i++) {
            As[lk + i][lrow] = av[i];
            Bs[lk + i][lrow] = wv[i];
        }
        __syncthreads();
        if (act) {
#pragma unroll
            for (int kk = 0; kk < 8; kk++) {
                float a[8], b[8];
                *(float4*)&a[0] = *(const float4*)&As[kk][ty * 8];
                *(float4*)&a[4] = *(const float4*)&As[kk][ty * 8 + 4];
                *(float4*)&b[0] = *(const float4*)&Bs[kk][tx * 8];
                *(float4*)&b[4] = *(const float4*)&Bs[kk][tx * 8 + 4];
#pragma unroll
                for (int i = 0; i < 8; i++)
#pragma unroll
                    for (int j = 0; j < 8; j++) acc[i][j] += a[i] * b[j];
            }
        }
    }

#pragma unroll
    for (int i = 0; i < 8; i++) {
        int lr = ty * 8 + i;
        if (lr >= rowlim) continue;
        int m = mbase + lr;
        int crow = (mode == 1) ? (((m & 255) << 7) + RANK[m >> 8]) : m;
        float* Cr = C + (size_t)crow * G4 + nbase + tx * 8;
        const float* p1 = b1 + nbase + tx * 8;
        const float* p2 = b2 + nbase + tx * 8;
#pragma unroll
        for (int j = 0; j < 8; j++) Cr[j] = acc[i][j] + p1[j] + p2[j];
    }
}

// ---------------- grid-wide barrier -----------------------------------------
__device__ __forceinline__ void gsync(unsigned int& lg) {
    __syncthreads();
    if (threadIdx.x == 0) {
        __threadfence();
        unsigned int target = lg + 1;
        if (atomicAdd(&BAR_CNT, 1u) == (unsigned)(NB_RECUR - 1)) {
            atomicExch(&BAR_CNT, 0u);
            __threadfence();
            BAR_GEN = target;
        } else {
            while (BAR_GEN < target) __nanosleep(64);
        }
    }
    lg++;
    __syncthreads();
}

// ---------------- tensor-core persistent recurrence --------------------------
// bf16 hi/lo 3-pass mma (fragment conventions identical to the numerically
// validated R11 k_gemm_tc). W_hh converted to fragments in smem ONCE; h
// exchanged between blocks as bf16 hi+lo planes; acc init = pre (bias fold).
#define MMA_BF16(C, A0, A1, A2, A3, B0, B1)                                   \
    asm volatile("mma.sync.aligned.m16n8k16.row.col.f32.bf16.bf16.f32 "       \
                 "{%0,%1,%2,%3}, {%4,%5,%6,%7}, {%8,%9}, {%0,%1,%2,%3};"      \
                 : "+f"((C)[0]), "+f"((C)[1]), "+f"((C)[2]), "+f"((C)[3])     \
                 : "r"(A0), "r"(A1), "r"(A2), "r"(A3), "r"(B0), "r"(B1))

struct RQ3 {
    const float* pre[2];
    const float* whh[2];
    __nv_bfloat16* hp[2];    // 4 planes: A_hi, A_lo, B_hi, B_lo (each BSZ*HSZ)
    float* out0[2];          // fp32, pre-offset by dir*512; nullptr = none
    float* hfin;             // fp32 final-h sink (l1 only)
    int rev[2];
    int ndirs;
};

template <int ROWS>
__global__ void __launch_bounds__(256, 1) k_recur3(RQ3 p) {
    constexpr int NW = ROWS / 32;            // mma warps (2 m-tiles each)
    constexpr int SN = (ROWS == 128) ? 8 : 4;
    extern __shared__ unsigned sm[];
    unsigned* WF  = sm;                       // [32 k16][4 gates][32 lanes][4] u32
    unsigned* AHI = sm + 16384;               // [ROWS][36] u32 (64-k chunk, hi)
    unsigned* ALO = AHI + ROWS * 36;          // [ROWS][36] u32 (lo)

    int tid = threadIdx.x;
    int wid = tid >> 5, lane = tid & 31;
    int lr = lane >> 2, lc = lane & 3;
    const int slab = BSZ * HSZ;

    int dir, j0, rbase;
    if (p.ndirs == 2) { dir = blockIdx.x >> 6; j0 = (blockIdx.x & 63) * 8; rbase = 0; }
    else              { dir = 0; j0 = (blockIdx.x >> 1) * 8; rbase = (blockIdx.x & 1) * 64; }

    const float* whh = p.whh[dir];
    const float* pre = p.pre[dir];
    __nv_bfloat16* hp = p.hp[dir];
    float* out0 = p.out0[dir];
    int rev = p.rev[dir];

    // ---- one-time W_hh -> bf16 hi/lo fragments in smem
    // entry e = (k16g*4 + g)*32 + lane': b-frag regs for n = j0 + lane'/4,
    // k = k16g*16 + (lane'%4)*2 (+1), and +8.  Stored [b0h, b1h, b0l, b1l].
    for (int e = tid; e < 4096; e += 256) {
        int ln   = e & 31;
        int g    = (e >> 5) & 3;
        int k16g = e >> 7;
        int jj   = ln >> 2;
        int kk   = k16g * 16 + (ln & 3) * 2;
        const float* wr = whh + (size_t)(g * 512 + j0 + jj) * 512 + kk;
        float w0 = wr[0], w1 = wr[1], w8 = wr[8], w9 = wr[9];
        float h0 = __bfloat162float(__float2bfloat16(w0));
        float h1 = __bfloat162float(__float2bfloat16(w1));
        float h8 = __bfloat162float(__float2bfloat16(w8));
        float h9 = __bfloat162float(__float2bfloat16(w9));
        unsigned* d = WF + (size_t)e * 4;
        d[0] = pack_bf16(w0, w1);
        d[1] = pack_bf16(w8, w9);
        d[2] = pack_bf16(w0 - h0, w1 - h1);
        d[3] = pack_bf16(w8 - h8, w9 - h9);
    }

    // staging assignment: (row, plane[, k-half])
    int srow, splane, sbase;
    if (ROWS == 128) { srow = tid & 127; splane = tid >> 7; sbase = 0; }
    else             { srow = tid & 63; splane = (tid >> 6) & 1; sbase = (tid >> 7) * 4; }

    bool ismma = (wid < NW);
    int w = wid;

    float creg[2][4], hreg[2][4];
#pragma unroll
    for (int mt = 0; mt < 2; mt++)
#pragma unroll
        for (int q = 0; q < 4; q++) { creg[mt][q] = 1.0f; hreg[mt][q] = 1.0f; }

    __syncthreads();     // WF ready
    unsigned lg = 0;

    for (int s = 0; s < SSZ; s++) {
        int tt = rev ? (SSZ - 1 - s) : s;
        int nact = NACT[tt];
        int nloc = nact - rbase;
        const __nv_bfloat16* hinh = hp + ((s & 1) ? 2 : 0) * slab;
        const __nv_bfloat16* hinl = hp + ((s & 1) ? 3 : 1) * slab;
        __nv_bfloat16* houth = hp + ((s & 1) ? 0 : 2) * slab;
        __nv_bfloat16* houtl = hp + ((s & 1) ? 1 : 3) * slab;
        bool do_stage = (rbase + srow) < nact;

        // ---- acc init = pre (gate bias); LDGs overlap with chunk-0 staging
        float acc[2][4][4];
        if (ismma) {
#pragma unroll
            for (int mt = 0; mt < 2; mt++) {
#pragma unroll
                for (int qh = 0; qh < 2; qh++) {
                    int row = rbase + w * 32 + mt * 16 + qh * 8 + lr;
                    const float* pb = pre + ((size_t)tt * BSZ + row) * G4 + j0 + 2 * lc;
                    bool a = row < nact;
#pragma unroll
                    for (int g = 0; g < 4; g++) {
                        float2 z = a ? *(const float2*)(pb + g * 512) : make_float2(0.f, 0.f);
                        acc[mt][g][qh * 2 + 0] = z.x;
                        acc[mt][g][qh * 2 + 1] = z.y;
                    }
                }
            }
        }

        // ---- prefetch chunk 0 of this thread's h plane
        uint4 stg[SN];
        const uint4* ssrc = (const uint4*)((splane ? hinl : hinh) +
                                           (size_t)(rbase + srow) * HSZ);
        if (do_stage) {
#pragma unroll
            for (int i = 0; i < SN; i++) stg[i] = ssrc[sbase + i];
        }

        for (int kc = 0; kc < 8; kc++) {             // 8 chunks of k=64
            __syncthreads();
            if (do_stage) {
                uint4* dst = (uint4*)((splane ? ALO : AHI) + srow * 36);
#pragma unroll
                for (int i = 0; i < SN; i++) dst[sbase + i] = stg[i];
            }
            __syncthreads();
            if (kc < 7 && do_stage) {                // pipeline next chunk
#pragma unroll
                for (int i = 0; i < SN; i++) stg[i] = ssrc[(kc + 1) * 8 + sbase + i];
            }
            if (ismma && w * 32 < nloc) {
#pragma unroll
                for (int k16l = 0; k16l < 4; k16l++) {
                    int k16g = kc * 4 + k16l;
                    const unsigned* wb = WF + ((size_t)k16g * 4) * 128 + lane * 4;
                    uint4 bf0 = *(const uint4*)(wb);
                    uint4 bf1 = *(const uint4*)(wb + 128);
                    uint4 bf2 = *(const uint4*)(wb + 256);
                    uint4 bf3 = *(const uint4*)(wb + 384);
                    int kw = k16l * 8 + lc;
#pragma unroll
                    for (int mt = 0; mt < 2; mt++) {
                        if (w * 32 + mt * 16 >= nloc) continue;
                        int rb0 = (w * 32 + mt * 16 + lr) * 36 + kw;
                        int rb1 = rb0 + 8 * 36;
                        unsigned a0h = AHI[rb0], a1h = AHI[rb1];
                        unsigned a2h = AHI[rb0 + 4], a3h = AHI[rb1 + 4];
                        unsigned a0l = ALO[rb0], a1l = ALO[rb1];
                        unsigned a2l = ALO[rb0 + 4], a3l = ALO[rb1 + 4];
                        MMA_BF16(acc[mt][0], a0h, a1h, a2h, a3h, bf0.x, bf0.y);
                        MMA_BF16(acc[mt][0], a0h, a1h, a2h, a3h, bf0.z, bf0.w);
                        MMA_BF16(acc[mt][0], a0l, a1l, a2l, a3l, bf0.x, bf0.y);
                        MMA_BF16(acc[mt][1], a0h, a1h, a2h, a3h, bf1.x, bf1.y);
                        MMA_BF16(acc[mt][1], a0h, a1h, a2h, a3h, bf1.z, bf1.w);
                        MMA_BF16(acc[mt][1], a0l, a1l, a2l, a3l, bf1.x, bf1.y);
                        MMA_BF16(acc[mt][2], a0h, a1h, a2h, a3h, bf2.x, bf2.y);
                        MMA_BF16(acc[mt][2], a0h, a1h, a2h, a3h, bf2.z, bf2.w);
                        MMA_BF16(acc[mt][2], a0l, a1l, a2l, a3l, bf2.x, bf2.y);
                        MMA_BF16(acc[mt][3], a0h, a1h, a2h, a3h, bf3.x, bf3.y);
                        MMA_BF16(acc[mt][3], a0h, a1h, a2h, a3h, bf3.z, bf3.w);
                        MMA_BF16(acc[mt][3], a0l, a1l, a2l, a3l, bf3.x, bf3.y);
                    }
                }
            }
        }

        // ---- gates (register-local: acc[mt][g][q] = 4 gates of cell q)
        if (ismma) {
#pragma unroll
            for (int mt = 0; mt < 2; mt++) {
#pragma unroll
                for (int qh = 0; qh < 2; qh++) {
                    int row = rbase + w * 32 + mt * 16 + qh * 8 + lr;
#pragma unroll
                    for (int qc = 0; qc < 2; qc++) {
                        int q = qh * 2 + qc;
                        if (row < nact) {
                            float zi = acc[mt][0][q], zf = acc[mt][1][q];
                            float zg = acc[mt][2][q], zo = acc[mt][3][q];
                            float cn = sigm(zf) * creg[mt][q] + sigm(zi) * tanhf(zg);
                            creg[mt][q] = cn;
                            hreg[mt][q] = sigm(zo) * tanhf(cn);
                        }
                    }
                    float h0 = hreg[mt][qh * 2], h1 = hreg[mt][qh * 2 + 1];
                    float h0h = __bfloat162float(__float2bfloat16(h0));
                    float h1h = __bfloat162float(__float2bfloat16(h1));
                    unsigned ph = pack_bf16(h0, h1);
                    unsigned pl = pack_bf16(h0 - h0h, h1 - h1h);
                    int cb = j0 + 2 * lc;
                    *(unsigned*)(houth + (size_t)row * HSZ + cb) = ph;
                    *(unsigned*)(houtl + (size_t)row * HSZ + cb) = pl;
                    if (out0) {
                        float2 o; o.x = h0; o.y = h1;
                        *(float2*)(out0 + ((size_t)tt * BSZ + row) * (2 * HSZ) + cb) = o;
                    }
                    if (p.hfin && s == SSZ - 1) {
                        float2 o; o.x = h0; o.y = h1;
                        *(float2*)(p.hfin + (size_t)row * HSZ + cb) = o;
                    }
                }
            }
        }
        gsync(lg);
    }
}

// ---------------- FC head ----------------------------------------------------
__global__ void k_fc(const float* __restrict__ h,
                     const float* __restrict__ fc1w, const float* __restrict__ fc1b,
                     const float* __restrict__ fcw,  const float* __restrict__ fcb,
                     float* __restrict__ out)
{
    __shared__ float tmp[HSZ];
    __shared__ float red[2][256];
    int b = blockIdx.x, tid = threadIdx.x;
    const float* hb = h + (size_t)RANK[b] * HSZ;

    for (int j = tid; j < HSZ; j += 256) {
        const float* w = fc1w + (size_t)j * HSZ;
        float s0 = 0.f, s1 = 0.f, s2 = 0.f, s3 = 0.f;
        for (int k = 0; k < HSZ; k += 4) {
            s0 += hb[k] * w[k];         s1 += hb[k + 1] * w[k + 1];
            s2 += hb[k + 2] * w[k + 2]; s3 += hb[k + 3] * w[k + 3];
        }
        tmp[j] = s0 + s1 + s2 + s3 + fc1b[j];
    }
    __syncthreads();
    float p0 = 0.f, p1 = 0.f;
    for (int k = tid; k < HSZ; k += 256) {
        p0 += tmp[k] * fcw[k];
        p1 += tmp[k] * fcw[HSZ + k];
    }
    red[0][tid] = p0; red[1][tid] = p1;
    __syncthreads();
    for (int off = 128; off > 0; off >>= 1) {
        if (tid < off) {
            red[0][tid] += red[0][tid + off];
            red[1][tid] += red[1][tid + off];
        }
        __syncthreads();
    }
    if (tid == 0) {
        out[b * 2 + 0] = red[0][0] + fcb[0];
        out[b * 2 + 1] = red[1][0] + fcb[1];
    }
}

// ---------------- host launch sequence ---------------------------------------
extern "C" void kernel_launch(void* const* d_in, const int* in_sizes, int n_in,
                              void* d_out, int out_size)
{
    const float* x          = (const float*)d_in[0];
    const float* w_ih_l0_f  = (const float*)d_in[1];
    const float* w_hh_l0_f  = (const float*)d_in[2];
    const float* b_ih_l0_f  = (const float*)d_in[3];
    const float* b_hh_l0_f  = (const float*)d_in[4];
    const float* w_ih_l0_r  = (const float*)d_in[5];
    const float* w_hh_l0_r  = (const float*)d_in[6];
    const float* b_ih_l0_r  = (const float*)d_in[7];
    const float* b_hh_l0_r  = (const float*)d_in[8];
    // d_in[9..12] = layer-1 forward (dead code: reference uses only hT_r)
    const float* w_ih_l1_r  = (const float*)d_in[13];
    const float* w_hh_l1_r  = (const float*)d_in[14];
    const float* b_ih_l1_r  = (const float*)d_in[15];
    const float* b_hh_l1_r  = (const float*)d_in[16];
    const float* fc1_w      = (const float*)d_in[17];
    const float* fc1_b      = (const float*)d_in[18];
    const float* fc_w       = (const float*)d_in[19];
    const float* fc_b       = (const float*)d_in[20];
    float* out = (float*)d_out;

    void* pv;
    cudaGetSymbolAddress(&pv, PRE0F);  float* pre0f = (float*)pv;
    cudaGetSymbolAddress(&pv, PRE0R);  float* pre0r = (float*)pv;
    cudaGetSymbolAddress(&pv, OUT0);   float* out0  = (float*)pv;
    cudaGetSymbolAddress(&pv, HP);     __nv_bfloat16* hpb = (__nv_bfloat16*)pv;
    cudaGetSymbolAddress(&pv, HFIN);   float* hfin  = (float*)pv;
    float* pre1 = pre0f;               // alias: PRE0F dead after l0 recurrence
    const int slab = BSZ * HSZ;
    const int M = BSZ * SSZ;

    const int SMR0 = (16384 + 128 * 36 * 2) * 4;   // 102400 B
    const int SMR1 = (16384 + 64 * 36 * 2) * 4;    //  83968 B
    cudaFuncSetAttribute(k_recur3<128>, cudaFuncAttributeMaxDynamicSharedMemorySize, SMR0);
    cudaFuncSetAttribute(k_recur3<64>,  cudaFuncAttributeMaxDynamicSharedMemorySize, SMR1);

    // 1) init + rank/NACT prep                                  (launch 1,2)
    k_init<<<768, 256>>>(x);
    k_prep<<<1, BSZ>>>();

    // 2) layer-0 input projections (fp32 SGEMM)                 (launch 3,4)
    dim3 gg(16, 256);
    k_gemm<<<gg, 256>>>(x, M, ESZ, w_ih_l0_f, b_ih_l0_f, b_hh_l0_f, pre0f, 1);
    k_gemm<<<gg, 256>>>(x, M, ESZ, w_ih_l0_r, b_ih_l0_r, b_hh_l0_r, pre0r, 1);

    // pad so ncu (-s 5 -c 1) lands on k_recur3<128>             (launch 5)
    k_reset<<<1, 1>>>();

    // 3) layer-0 recurrence (tensor-core, both dirs)            (launch 6)
    RQ3 rq0;
    rq0.pre[0] = pre0f;  rq0.whh[0] = w_hh_l0_f;
    rq0.hp[0]  = hpb;                rq0.out0[0] = out0;        rq0.rev[0] = 0;
    rq0.pre[1] = pre0r;  rq0.whh[1] = w_hh_l0_r;
    rq0.hp[1]  = hpb + 4 * slab;     rq0.out0[1] = out0 + HSZ;  rq0.rev[1] = 1;
    rq0.hfin = nullptr;  rq0.ndirs = 2;
    k_recur3<128><<<NB_RECUR, 256, SMR0>>>(rq0);

    // 4) layer-1 (reverse only) projection                      (launch 7)
    k_gemm<<<gg, 256>>>(out0, M, 2 * HSZ, w_ih_l1_r, b_ih_l1_r, b_hh_l1_r, pre1, 2);

    // 5) layer-1 reverse recurrence                             (launch 8,9)
    k_reset<<<1, 1>>>();
    RQ3 rq1;
    rq1.pre[0] = pre1;   rq1.whh[0] = w_hh_l1_r;
    rq1.hp[0]  = hpb + 8 * slab;     rq1.out0[0] = nullptr;     rq1.rev[0] = 1;
    rq1.pre[1] = nullptr; rq1.whh[1] = nullptr;
    rq1.hp[1]  = nullptr;            rq1.out0[1] = nullptr;     rq1.rev[1] = 0;
    rq1.hfin = hfin;     rq1.ndirs = 1;
    k_recur3<64><<<NB_RECUR, 256, SMR1>>>(rq1);

    // 6) FC head on fp32 final h (rank rows)                    (launch 10)
    k_fc<<<BSZ, 256>>>(hfin, fc1_w, fc1_b, fc_w, fc_b, out);
}

// round 15
// speedup vs baseline: 1.8710x; 1.0441x over previous
#include <cuda_runtime.h>
#include <cuda_bf16.h>
#include <math.h>

// Problem constants
#define BSZ 128
#define SSZ 256
#define ESZ 300
#define HSZ 512
#define G4  2048
#define NB_RECUR 128       // persistent grid: 1 block/SM, co-resident wave 1

// ---------------- scratch (static device memory) -----------------------------
__device__ float PRE0F[SSZ * BSZ * G4];          // [t][r][4H] l0 fwd (aliased: l1 rev)
__device__ float PRE0R[SSZ * BSZ * G4];          // [t][r][4H] l0 rev
__device__ float OUT0 [SSZ * BSZ * 2 * HSZ];     // [t][r][2H] fp32 concat(fwd,rev)
// h exchange planes (bf16): slot*4 + {A_hi, A_lo, B_hi, B_lo}; slots: l0f,l0r,l1r
__device__ __nv_bfloat16 HP[12][BSZ * HSZ];
__device__ float HFIN[BSZ * HSZ];                // fp32 final h of l1 (rank rows)
__device__ int   LEN[BSZ];
__device__ int   RANK[BSZ];
__device__ int   NACT[SSZ];
// tree barrier: 2 domains x 8 leaves, each leaf counter on its own 128B line
__device__ unsigned BAR_LEAF[2 * 8 * 32];
__device__ unsigned BAR_ROOT[2 * 32];
__device__ volatile unsigned BAR_G2[2];

__device__ __forceinline__ float sigm(float x) { return 1.0f / (1.0f + expf(-x)); }

__device__ __forceinline__ unsigned pack_bf16(float x, float y) {
    __nv_bfloat16 bx = __float2bfloat16(x), by = __float2bfloat16(y);
    return (unsigned)__bfloat16_as_ushort(bx) | ((unsigned)__bfloat16_as_ushort(by) << 16);
}

// ---------------- init ------------------------------------------------------
__global__ void k_init(const float* __restrict__ x) {
    int tid = blockIdx.x * blockDim.x + threadIdx.x;
    const int slab = BSZ * HSZ;
    if (tid < 3 * slab) {                 // h bufA planes: hi=1.0, lo=0
        int w = tid / slab, i = tid - w * slab;
        HP[w * 4 + 0][i] = __float2bfloat16(1.0f);
        HP[w * 4 + 1][i] = __float2bfloat16(0.0f);
    }
    if (tid < BSZ) {
        int v = (int)x[((size_t)tid * SSZ + (SSZ - 1)) * ESZ];
        LEN[tid] = v < SSZ ? v : SSZ;
    }
    if (tid < 512) BAR_LEAF[tid] = 0;
    if (tid < 64)  BAR_ROOT[tid] = 0;
    if (tid < 2)   BAR_G2[tid] = 0;
}

__global__ void k_reset() {
    int tid = threadIdx.x;
    if (tid < 512) BAR_LEAF[tid] = 0;
    if (tid < 64)  BAR_ROOT[tid] = 0;
    if (tid < 2)   BAR_G2[tid] = 0;
}

// ---------------- prep: rank permutation + NACT ------------------------------
__global__ void k_prep() {
    __shared__ int sl[BSZ];
    int b = threadIdx.x;
    sl[b] = LEN[b];
    __syncthreads();
    int mylen = sl[b];
    int rk = 0;
    for (int o = 0; o < BSZ; o++) {
        int lo = sl[o];
        rk += (lo > mylen) || (lo == mylen && o < b);
    }
    RANK[b] = rk;
    for (int t = b; t < SSZ; t += BSZ) {
        int c = 0;
        for (int o = 0; o < BSZ; o++) c += (sl[o] > t);
        NACT[t] = c;
    }
}

// ---------------- fp32 NT-GEMM (input projections; occ=2) -------------------
__global__ void __launch_bounds__(256, 2) k_gemm(
    const float* __restrict__ A, int M, int K,
    const float* __restrict__ W,
    const float* __restrict__ b1, const float* __restrict__ b2,
    float* __restrict__ C, int mode)
{
    __shared__ float As[8][128];
    __shared__ float Bs[8][128];

    int tid = threadIdx.x;
    int ty = tid >> 4, tx = tid & 15;
    int mbase = blockIdx.y * 128;
    int nbase = blockIdx.x * 128;

    int rowlim = 128;
    if (mode == 1) {
        int b = mbase >> 8, t0 = mbase & 255;
        rowlim = LEN[b] - t0;
        if (rowlim > 128) rowlim = 128;
        if (rowlim <= 0) return;
    } else if (mode == 2) {
        int t = mbase >> 7;
        rowlim = NACT[t];
        if (rowlim <= 0) return;
    }
    bool act = (ty * 8) < rowlim;

    float acc[8][8];
#pragma unroll
    for (int i = 0; i < 8; i++)
#pragma unroll
        for (int j = 0; j < 8; j++) acc[i][j] = 0.0f;

    int lrow = tid >> 1;
    int lk   = (tid & 1) * 4;
    const float* Arow = A + (size_t)(mbase + lrow) * K;
    const float* Wrow = W + (size_t)(nbase + lrow) * K;

    for (int kb = 0; kb < K; kb += 8) {
        float av[4], wv[4];
        if (kb + lk + 3 < K) {
            float4 t = *(const float4*)(Arow + kb + lk);
            av[0] = t.x; av[1] = t.y; av[2] = t.z; av[3] = t.w;
            float4 u = *(const float4*)(Wrow + kb + lk);
            wv[0] = u.x; wv[1] = u.y; wv[2] = u.z; wv[3] = u.w;
        } else {
#pragma unroll
            for (int i = 0; i < 4; i++) {
                int k = kb + lk + i;
                av[i] = (k < K) ? Arow[k] : 0.0f;
                wv[i] = (k < K) ? Wrow[k] : 0.0f;
            }
        }
        __syncthreads();
#pragma unroll
        for (int i = 0; i < 4; i++) {
            As[lk + i][lrow] = av[i];
            Bs[lk + i][lrow] = wv[i];
        }
        __syncthreads();
        if (act) {
#pragma unroll
            for (int kk = 0; kk < 8; kk++) {
                float a[8], b[8];
                *(float4*)&a[0] = *(const float4*)&As[kk][ty * 8];
                *(float4*)&a[4] = *(const float4*)&As[kk][ty * 8 + 4];
                *(float4*)&b[0] = *(const float4*)&Bs[kk][tx * 8];
                *(float4*)&b[4] = *(const float4*)&Bs[kk][tx * 8 + 4];
#pragma unroll
                for (int i = 0; i < 8; i++)
#pragma unroll
                    for (int j = 0; j < 8; j++) acc[i][j] += a[i] * b[j];
            }
        }
    }

#pragma unroll
    for (int i = 0; i < 8; i++) {
        int lr = ty * 8 + i;
        if (lr >= rowlim) continue;
        int m = mbase + lr;
        int crow = (mode == 1) ? (((m & 255) << 7) + RANK[m >> 8]) : m;
        float* Cr = C + (size_t)crow * G4 + nbase + tx * 8;
        const float* p1 = b1 + nbase + tx * 8;
        const float* p2 = b2 + nbase + tx * 8;
#pragma unroll
        for (int j = 0; j < 8; j++) Cr[j] = acc[i][j] + p1[j] + p2[j];
    }
}

// ---------------- tree grid barrier (per-domain) -----------------------------
// 8 leaf counters per domain on distinct 128B lines + 1 root; serialized atomic
// chain ~650 cyc instead of ~3.5k for 128 same-address arrivals.
__device__ __forceinline__ void gsync3(int dom, int lidx, int leafsz, unsigned& lg) {
    __syncthreads();
    if (threadIdx.x == 0) {
        __threadfence();
        unsigned target = lg + 1;
        int leaf = lidx & 7;
        if (atomicAdd(&BAR_LEAF[(dom * 8 + leaf) * 32], 1u) == (unsigned)(leafsz - 1)) {
            atomicExch(&BAR_LEAF[(dom * 8 + leaf) * 32], 0u);
            if (atomicAdd(&BAR_ROOT[dom * 32], 1u) == 7u) {
                atomicExch(&BAR_ROOT[dom * 32], 0u);
                __threadfence();
                BAR_G2[dom] = target;
            }
        }
        while (BAR_G2[dom] < target) __nanosleep(32);
        __threadfence();
    }
    lg++;
    __syncthreads();
}

// ---------------- tensor-core persistent recurrence --------------------------
// bf16 hi/lo 3-pass mma; W_hh fragments resident in smem; h exchanged as bf16
// hi+lo planes; acc init = pre. l0: two independent 64-block sync domains
// (one per direction). l1: one 128-block domain.
#define MMA_BF16(C, A0, A1, A2, A3, B0, B1)                                   \
    asm volatile("mma.sync.aligned.m16n8k16.row.col.f32.bf16.bf16.f32 "       \
                 "{%0,%1,%2,%3}, {%4,%5,%6,%7}, {%8,%9}, {%0,%1,%2,%3};"      \
                 : "+f"((C)[0]), "+f"((C)[1]), "+f"((C)[2]), "+f"((C)[3])     \
                 : "r"(A0), "r"(A1), "r"(A2), "r"(A3), "r"(B0), "r"(B1))

struct RQ3 {
    const float* pre[2];
    const float* whh[2];
    __nv_bfloat16* hp[2];    // 4 planes: A_hi, A_lo, B_hi, B_lo (each BSZ*HSZ)
    float* out0[2];          // fp32, pre-offset by dir*512; nullptr = none
    float* hfin;             // fp32 final-h sink (l1 only)
    int rev[2];
    int ndirs;
};

template <int ROWS>
__global__ void __launch_bounds__(256, 1) k_recur3(RQ3 p) {
    constexpr int NW = ROWS / 32;            // mma warps (2 m-tiles each)
    constexpr int SN = (ROWS == 128) ? 8 : 4;
    extern __shared__ unsigned sm[];
    unsigned* WF  = sm;                       // [32 k16][4 gates][32 lanes][4] u32
    unsigned* AHI = sm + 16384;               // [ROWS][36] u32 (64-k chunk, hi)
    unsigned* ALO = AHI + ROWS * 36;          // [ROWS][36] u32 (lo)

    int tid = threadIdx.x;
    int wid = tid >> 5, lane = tid & 31;
    int lr = lane >> 2, lc = lane & 3;
    const int slab = BSZ * HSZ;

    int dir, j0, rbase, dom, lidx, leafsz;
    if (p.ndirs == 2) {
        dir = blockIdx.x >> 6; j0 = (blockIdx.x & 63) * 8; rbase = 0;
        dom = dir; lidx = blockIdx.x & 63; leafsz = 8;        // 64-block domain
    } else {
        dir = 0; j0 = (blockIdx.x >> 1) * 8; rbase = (blockIdx.x & 1) * 64;
        dom = 0; lidx = blockIdx.x; leafsz = 16;              // 128-block domain
    }

    const float* whh = p.whh[dir];
    const float* pre = p.pre[dir];
    __nv_bfloat16* hp = p.hp[dir];
    float* out0 = p.out0[dir];
    int rev = p.rev[dir];

    // ---- one-time W_hh -> bf16 hi/lo fragments in smem
    for (int e = tid; e < 4096; e += 256) {
        int ln   = e & 31;
        int g    = (e >> 5) & 3;
        int k16g = e >> 7;
        int jj   = ln >> 2;
        int kk   = k16g * 16 + (ln & 3) * 2;
        const float* wr = whh + (size_t)(g * 512 + j0 + jj) * 512 + kk;
        float w0 = wr[0], w1 = wr[1], w8 = wr[8], w9 = wr[9];
        float h0 = __bfloat162float(__float2bfloat16(w0));
        float h1 = __bfloat162float(__float2bfloat16(w1));
        float h8 = __bfloat162float(__float2bfloat16(w8));
        float h9 = __bfloat162float(__float2bfloat16(w9));
        unsigned* d = WF + (size_t)e * 4;
        d[0] = pack_bf16(w0, w1);
        d[1] = pack_bf16(w8, w9);
        d[2] = pack_bf16(w0 - h0, w1 - h1);
        d[3] = pack_bf16(w8 - h8, w9 - h9);
    }

    // staging assignment: (row, plane[, k-half])
    int srow, splane, sbase;
    if (ROWS == 128) { srow = tid & 127; splane = tid >> 7; sbase = 0; }
    else             { srow = tid & 63; splane = (tid >> 6) & 1; sbase = (tid >> 7) * 4; }

    bool ismma = (wid < NW);
    int w = wid;

    float creg[2][4], hreg[2][4];
#pragma unroll
    for (int mt = 0; mt < 2; mt++)
#pragma unroll
        for (int q = 0; q < 4; q++) { creg[mt][q] = 1.0f; hreg[mt][q] = 1.0f; }

    __syncthreads();     // WF ready
    unsigned lg = 0;

    for (int s = 0; s < SSZ; s++) {
        int tt = rev ? (SSZ - 1 - s) : s;
        int nact = NACT[tt];
        int nloc = nact - rbase;
        const __nv_bfloat16* hinh = hp + ((s & 1) ? 2 : 0) * slab;
        const __nv_bfloat16* hinl = hp + ((s & 1) ? 3 : 1) * slab;
        __nv_bfloat16* houth = hp + ((s & 1) ? 0 : 2) * slab;
        __nv_bfloat16* houtl = hp + ((s & 1) ? 1 : 3) * slab;
        bool do_stage = (rbase + srow) < nact;

        // ---- acc init = pre (gate bias); LDGs overlap with chunk-0 staging
        float acc[2][4][4];
        if (ismma) {
#pragma unroll
            for (int mt = 0; mt < 2; mt++) {
#pragma unroll
                for (int qh = 0; qh < 2; qh++) {
                    int row = rbase + w * 32 + mt * 16 + qh * 8 + lr;
                    const float* pb = pre + ((size_t)tt * BSZ + row) * G4 + j0 + 2 * lc;
                    bool a = row < nact;
#pragma unroll
                    for (int g = 0; g < 4; g++) {
                        float2 z = a ? *(const float2*)(pb + g * 512) : make_float2(0.f, 0.f);
                        acc[mt][g][qh * 2 + 0] = z.x;
                        acc[mt][g][qh * 2 + 1] = z.y;
                    }
                }
            }
        }

        // ---- prefetch chunk 0 of this thread's h plane
        uint4 stg[SN];
        const uint4* ssrc = (const uint4*)((splane ? hinl : hinh) +
                                           (size_t)(rbase + srow) * HSZ);
        if (do_stage) {
#pragma unroll
            for (int i = 0; i < SN; i++) stg[i] = ssrc[sbase + i];
        }

        for (int kc = 0; kc < 8; kc++) {             // 8 chunks of k=64
            __syncthreads();
            if (do_stage) {
                uint4* dst = (uint4*)((splane ? ALO : AHI) + srow * 36);
#pragma unroll
                for (int i = 0; i < SN; i++) dst[sbase + i] = stg[i];
            }
            __syncthreads();
            if (kc < 7 && do_stage) {                // pipeline next chunk
#pragma unroll
                for (int i = 0; i < SN; i++) stg[i] = ssrc[(kc + 1) * 8 + sbase + i];
            }
            if (ismma && w * 32 < nloc) {
#pragma unroll
                for (int k16l = 0; k16l < 4; k16l++) {
                    int k16g = kc * 4 + k16l;
                    const unsigned* wb = WF + ((size_t)k16g * 4) * 128 + lane * 4;
                    uint4 bf0 = *(const uint4*)(wb);
                    uint4 bf1 = *(const uint4*)(wb + 128);
                    uint4 bf2 = *(const uint4*)(wb + 256);
                    uint4 bf3 = *(const uint4*)(wb + 384);
                    int kw = k16l * 8 + lc;
#pragma unroll
                    for (int mt = 0; mt < 2; mt++) {
                        if (w * 32 + mt * 16 >= nloc) continue;
                        int rb0 = (w * 32 + mt * 16 + lr) * 36 + kw;
                        int rb1 = rb0 + 8 * 36;
                        unsigned a0h = AHI[rb0], a1h = AHI[rb1];
                        unsigned a2h = AHI[rb0 + 4], a3h = AHI[rb1 + 4];
                        unsigned a0l = ALO[rb0], a1l = ALO[rb1];
                        unsigned a2l = ALO[rb0 + 4], a3l = ALO[rb1 + 4];
                        MMA_BF16(acc[mt][0], a0h, a1h, a2h, a3h, bf0.x, bf0.y);
                        MMA_BF16(acc[mt][0], a0h, a1h, a2h, a3h, bf0.z, bf0.w);
                        MMA_BF16(acc[mt][0], a0l, a1l, a2l, a3l, bf0.x, bf0.y);
                        MMA_BF16(acc[mt][1], a0h, a1h, a2h, a3h, bf1.x, bf1.y);
                        MMA_BF16(acc[mt][1], a0h, a1h, a2h, a3h, bf1.z, bf1.w);
                        MMA_BF16(acc[mt][1], a0l, a1l, a2l, a3l, bf1.x, bf1.y);
                        MMA_BF16(acc[mt][2], a0h, a1h, a2h, a3h, bf2.x, bf2.y);
                        MMA_BF16(acc[mt][2], a0h, a1h, a2h, a3h, bf2.z, bf2.w);
                        MMA_BF16(acc[mt][2], a0l, a1l, a2l, a3l, bf2.x, bf2.y);
                        MMA_BF16(acc[mt][3], a0h, a1h, a2h, a3h, bf3.x, bf3.y);
                        MMA_BF16(acc[mt][3], a0h, a1h, a2h, a3h, bf3.z, bf3.w);
                        MMA_BF16(acc[mt][3], a0l, a1l, a2l, a3l, bf3.x, bf3.y);
                    }
                }
            }
        }

        // ---- gates (register-local: acc[mt][g][q] = 4 gates of cell q)
        if (ismma) {
#pragma unroll
            for (int mt = 0; mt < 2; mt++) {
#pragma unroll
                for (int qh = 0; qh < 2; qh++) {
                    int row = rbase + w * 32 + mt * 16 + qh * 8 + lr;
#pragma unroll
                    for (int qc = 0; qc < 2; qc++) {
                        int q = qh * 2 + qc;
                        if (row < nact) {
                            float zi = acc[mt][0][q], zf = acc[mt][1][q];
                            float zg = acc[mt][2][q], zo = acc[mt][3][q];
                            float cn = sigm(zf) * creg[mt][q] + sigm(zi) * tanhf(zg);
                            creg[mt][q] = cn;
                            hreg[mt][q] = sigm(zo) * tanhf(cn);
                        }
                    }
                    float h0 = hreg[mt][qh * 2], h1 = hreg[mt][qh * 2 + 1];
                    float h0h = __bfloat162float(__float2bfloat16(h0));
                    float h1h = __bfloat162float(__float2bfloat16(h1));
                    unsigned ph = pack_bf16(h0, h1);
                    unsigned pl = pack_bf16(h0 - h0h, h1 - h1h);
                    int cb = j0 + 2 * lc;
                    *(unsigned*)(houth + (size_t)row * HSZ + cb) = ph;
                    *(unsigned*)(houtl + (size_t)row * HSZ + cb) = pl;
                    if (out0) {
                        float2 o; o.x = h0; o.y = h1;
                        *(float2*)(out0 + ((size_t)tt * BSZ + row) * (2 * HSZ) + cb) = o;
                    }
                    if (p.hfin && s == SSZ - 1) {
                        float2 o; o.x = h0; o.y = h1;
                        *(float2*)(p.hfin + (size_t)row * HSZ + cb) = o;
                    }
                }
            }
        }
        gsync3(dom, lidx, leafsz, lg);
    }
}

// ---------------- FC head ----------------------------------------------------
__global__ void k_fc(const float* __restrict__ h,
                     const float* __restrict__ fc1w, const float* __restrict__ fc1b,
                     const float* __restrict__ fcw,  const float* __restrict__ fcb,
                     float* __restrict__ out)
{
    __shared__ float tmp[HSZ];
    __shared__ float red[2][256];
    int b = blockIdx.x, tid = threadIdx.x;
    const float* hb = h + (size_t)RANK[b] * HSZ;

    for (int j = tid; j < HSZ; j += 256) {
        const float* w = fc1w + (size_t)j * HSZ;
        float s0 = 0.f, s1 = 0.f, s2 = 0.f, s3 = 0.f;
        for (int k = 0; k < HSZ; k += 4) {
            s0 += hb[k] * w[k];         s1 += hb[k + 1] * w[k + 1];
            s2 += hb[k + 2] * w[k + 2]; s3 += hb[k + 3] * w[k + 3];
        }
        tmp[j] = s0 + s1 + s2 + s3 + fc1b[j];
    }
    __syncthreads();
    float p0 = 0.f, p1 = 0.f;
    for (int k = tid; k < HSZ; k += 256) {
        p0 += tmp[k] * fcw[k];
        p1 += tmp[k] * fcw[HSZ + k];
    }
    red[0][tid] = p0; red[1][tid] = p1;
    __syncthreads();
    for (int off = 128; off > 0; off >>= 1) {
        if (tid < off) {
            red[0][tid] += red[0][tid + off];
            red[1][tid] += red[1][tid + off];
        }
        __syncthreads();
    }
    if (tid == 0) {
        out[b * 2 + 0] = red[0][0] + fcb[0];
        out[b * 2 + 1] = red[1][0] + fcb[1];
    }
}

// ---------------- host launch sequence ---------------------------------------
extern "C" void kernel_launch(void* const* d_in, const int* in_sizes, int n_in,
                              void* d_out, int out_size)
{
    const float* x          = (const float*)d_in[0];
    const float* w_ih_l0_f  = (const float*)d_in[1];
    const float* w_hh_l0_f  = (const float*)d_in[2];
    const float* b_ih_l0_f  = (const float*)d_in[3];
    const float* b_hh_l0_f  = (const float*)d_in[4];
    const float* w_ih_l0_r  = (const float*)d_in[5];
    const float* w_hh_l0_r  = (const float*)d_in[6];
    const float* b_ih_l0_r  = (const float*)d_in[7];
    const float* b_hh_l0_r  = (const float*)d_in[8];
    // d_in[9..12] = layer-1 forward (dead code: reference uses only hT_r)
    const float* w_ih_l1_r  = (const float*)d_in[13];
    const float* w_hh_l1_r  = (const float*)d_in[14];
    const float* b_ih_l1_r  = (const float*)d_in[15];
    const float* b_hh_l1_r  = (const float*)d_in[16];
    const float* fc1_w      = (const float*)d_in[17];
    const float* fc1_b      = (const float*)d_in[18];
    const float* fc_w       = (const float*)d_in[19];
    const float* fc_b       = (const float*)d_in[20];
    float* out = (float*)d_out;

    void* pv;
    cudaGetSymbolAddress(&pv, PRE0F);  float* pre0f = (float*)pv;
    cudaGetSymbolAddress(&pv, PRE0R);  float* pre0r = (float*)pv;
    cudaGetSymbolAddress(&pv, OUT0);   float* out0  = (float*)pv;
    cudaGetSymbolAddress(&pv, HP);     __nv_bfloat16* hpb = (__nv_bfloat16*)pv;
    cudaGetSymbolAddress(&pv, HFIN);   float* hfin  = (float*)pv;
    float* pre1 = pre0f;               // alias: PRE0F dead after l0 recurrence
    const int slab = BSZ * HSZ;
    const int M = BSZ * SSZ;

    const int SMR0 = (16384 + 128 * 36 * 2) * 4;   // 102400 B
    const int SMR1 = (16384 + 64 * 36 * 2) * 4;    //  83968 B
    cudaFuncSetAttribute(k_recur3<128>, cudaFuncAttributeMaxDynamicSharedMemorySize, SMR0);
    cudaFuncSetAttribute(k_recur3<64>,  cudaFuncAttributeMaxDynamicSharedMemorySize, SMR1);

    // 1) init + rank/NACT prep                                  (launch 1,2)
    k_init<<<768, 256>>>(x);
    k_prep<<<1, BSZ>>>();

    // 2) layer-0 input projections (fp32 SGEMM, occ=2)          (launch 3,4)
    dim3 gg(16, 256);
    k_gemm<<<gg, 256>>>(x, M, ESZ, w_ih_l0_f, b_ih_l0_f, b_hh_l0_f, pre0f, 1);
    k_gemm<<<gg, 256>>>(x, M, ESZ, w_ih_l0_r, b_ih_l0_r, b_hh_l0_r, pre0r, 1);

    // pad so ncu (-s 5 -c 1) lands on k_recur3<128>             (launch 5)
    k_reset<<<1, 512>>>();

    // 3) layer-0 recurrence (tensor-core, 2 independent domains) (launch 6)
    RQ3 rq0;
    rq0.pre[0] = pre0f;  rq0.whh[0] = w_hh_l0_f;
    rq0.hp[0]  = hpb;                rq0.out0[0] = out0;        rq0.rev[0] = 0;
    rq0.pre[1] = pre0r;  rq0.whh[1] = w_hh_l0_r;
    rq0.hp[1]  = hpb + 4 * slab;     rq0.out0[1] = out0 + HSZ;  rq0.rev[1] = 1;
    rq0.hfin = nullptr;  rq0.ndirs = 2;
    k_recur3<128><<<NB_RECUR, 256, SMR0>>>(rq0);

    // 4) layer-1 (reverse only) projection                      (launch 7)
    k_gemm<<<gg, 256>>>(out0, M, 2 * HSZ, w_ih_l1_r, b_ih_l1_r, b_hh_l1_r, pre1, 2);

    // 5) layer-1 reverse recurrence                             (launch 8,9)
    k_reset<<<1, 512>>>();
    RQ3 rq1;
    rq1.pre[0] = pre1;   rq1.whh[0] = w_hh_l1_r;
    rq1.hp[0]  = hpb + 8 * slab;     rq1.out0[0] = nullptr;     rq1.rev[0] = 1;
    rq1.pre[1] = nullptr; rq1.whh[1] = nullptr;
    rq1.hp[1]  = nullptr;            rq1.out0[1] = nullptr;     rq1.rev[1] = 0;
    rq1.hfin = hfin;     rq1.ndirs = 1;
    k_recur3<64><<<NB_RECUR, 256, SMR1>>>(rq1);

    // 6) FC head on fp32 final h (rank rows)                    (launch 10)
    k_fc<<<BSZ, 256>>>(hfin, fc1_w, fc1_b, fc_w, fc_b, out);
}

// round 16
// speedup vs baseline: 1.9849x; 1.0609x over previous
#include <cuda_runtime.h>
#include <cuda_bf16.h>
#include <math.h>

// Problem constants
#define BSZ 128
#define SSZ 256
#define ESZ 300
#define HSZ 512
#define G4  2048
#define NB_RECUR 128       // persistent grid: 1 block/SM, co-resident wave 1

// ---------------- scratch (static device memory) -----------------------------
__device__ float PRE0F[SSZ * BSZ * G4];          // [t][r][4H] l0 fwd (aliased: l1 rev)
__device__ float PRE0R[SSZ * BSZ * G4];          // [t][r][4H] l0 rev
__device__ float OUT0 [SSZ * BSZ * 2 * HSZ];     // [t][r][2H] fp32 concat(fwd,rev)
// h exchange planes (bf16): slot*4 + {A_hi, A_lo, B_hi, B_lo}; slots: l0f,l0r,l1r
__device__ __nv_bfloat16 HP[12][BSZ * HSZ];
__device__ float HFIN[BSZ * HSZ];                // fp32 final h of l1 (rank rows)
__device__ int   LEN[BSZ];
__device__ int   RANK[BSZ];
__device__ int   NACT[SSZ];
// tree barrier: 3 domains (l0f, l0r, l1) x 8 leaves, each on its own 128B line
__device__ unsigned BAR_LEAF[3 * 8 * 32];
__device__ unsigned BAR_ROOT[3 * 32];
__device__ volatile unsigned BAR_G2[3];

__device__ __forceinline__ float sigm(float x) { return 1.0f / (1.0f + expf(-x)); }

__device__ __forceinline__ unsigned pack_bf16(float x, float y) {
    __nv_bfloat16 bx = __float2bfloat16(x), by = __float2bfloat16(y);
    return (unsigned)__bfloat16_as_ushort(bx) | ((unsigned)__bfloat16_as_ushort(by) << 16);
}

// ---------------- init ------------------------------------------------------
__global__ void k_init(const float* __restrict__ x) {
    int tid = blockIdx.x * blockDim.x + threadIdx.x;
    const int slab = BSZ * HSZ;
    if (tid < 3 * slab) {                 // h bufA planes: hi=1.0, lo=0
        int w = tid / slab, i = tid - w * slab;
        HP[w * 4 + 0][i] = __float2bfloat16(1.0f);
        HP[w * 4 + 1][i] = __float2bfloat16(0.0f);
    }
    if (tid < BSZ) {
        int v = (int)x[((size_t)tid * SSZ + (SSZ - 1)) * ESZ];
        LEN[tid] = v < SSZ ? v : SSZ;
    }
    if (tid < 768) BAR_LEAF[tid] = 0;
    if (tid < 96)  BAR_ROOT[tid] = 0;
    if (tid < 3)   BAR_G2[tid] = 0;
}

// ---------------- prep: rank permutation + NACT ------------------------------
__global__ void k_prep() {
    __shared__ int sl[BSZ];
    int b = threadIdx.x;
    sl[b] = LEN[b];
    __syncthreads();
    int mylen = sl[b];
    int rk = 0;
    for (int o = 0; o < BSZ; o++) {
        int lo = sl[o];
        rk += (lo > mylen) || (lo == mylen && o < b);
    }
    RANK[b] = rk;
    for (int t = b; t < SSZ; t += BSZ) {
        int c = 0;
        for (int o = 0; o < BSZ; o++) c += (sl[o] > t);
        NACT[t] = c;
    }
}

// ---------------- fp32 NT-GEMM (input projections) ---------------------------
// blockIdx.z selects weight/bias/output set (fused l0 fwd+rev in one launch).
struct GP {
    const float* W[2];
    const float* b1[2];
    const float* b2[2];
    float* C[2];
};

__global__ void __launch_bounds__(256, 2) k_gemm(
    const float* __restrict__ A, int M, int K, GP gp, int mode)
{
    __shared__ float As[8][128];
    __shared__ float Bs[8][128];

    const float* W  = gp.W[blockIdx.z];
    const float* b1 = gp.b1[blockIdx.z];
    const float* b2 = gp.b2[blockIdx.z];
    float* C        = gp.C[blockIdx.z];

    int tid = threadIdx.x;
    int ty = tid >> 4, tx = tid & 15;
    int mbase = blockIdx.y * 128;
    int nbase = blockIdx.x * 128;

    int rowlim = 128;
    if (mode == 1) {
        int b = mbase >> 8, t0 = mbase & 255;
        rowlim = LEN[b] - t0;
        if (rowlim > 128) rowlim = 128;
        if (rowlim <= 0) return;
    } else if (mode == 2) {
        int t = mbase >> 7;
        rowlim = NACT[t];
        if (rowlim <= 0) return;
    }
    bool act = (ty * 8) < rowlim;

    float acc[8][8];
#pragma unroll
    for (int i = 0; i < 8; i++)
#pragma unroll
        for (int j = 0; j < 8; j++) acc[i][j] = 0.0f;

    int lrow = tid >> 1;
    int lk   = (tid & 1) * 4;
    const float* Arow = A + (size_t)(mbase + lrow) * K;
    const float* Wrow = W + (size_t)(nbase + lrow) * K;

    for (int kb = 0; kb < K; kb += 8) {
        float av[4], wv[4];
        if (kb + lk + 3 < K) {
            float4 t = *(const float4*)(Arow + kb + lk);
            av[0] = t.x; av[1] = t.y; av[2] = t.z; av[3] = t.w;
            float4 u = *(const float4*)(Wrow + kb + lk);
            wv[0] = u.x; wv[1] = u.y; wv[2] = u.z; wv[3] = u.w;
        } else {
#pragma unroll
            for (int i = 0; i < 4; i++) {
                int k = kb + lk + i;
                av[i] = (k < K) ? Arow[k] : 0.0f;
                wv[i] = (k < K) ? Wrow[k] : 0.0f;
            }
        }
        __syncthreads();
#pragma unroll
        for (int i = 0; i < 4; i++) {
            As[lk + i][lrow] = av[i];
            Bs[lk + i][lrow] = wv[i];
        }
        __syncthreads();
        if (act) {
#pragma unroll
            for (int kk = 0; kk < 8; kk++) {
                float a[8], b[8];
                *(float4*)&a[0] = *(const float4*)&As[kk][ty * 8];
                *(float4*)&a[4] = *(const float4*)&As[kk][ty * 8 + 4];
                *(float4*)&b[0] = *(const float4*)&Bs[kk][tx * 8];
                *(float4*)&b[4] = *(const float4*)&Bs[kk][tx * 8 + 4];
#pragma unroll
                for (int i = 0; i < 8; i++)
#pragma unroll
                    for (int j = 0; j < 8; j++) acc[i][j] += a[i] * b[j];
            }
        }
    }

#pragma unroll
    for (int i = 0; i < 8; i++) {
        int lr = ty * 8 + i;
        if (lr >= rowlim) continue;
        int m = mbase + lr;
        int crow = (mode == 1) ? (((m & 255) << 7) + RANK[m >> 8]) : m;
        float* Cr = C + (size_t)crow * G4 + nbase + tx * 8;
        const float* p1 = b1 + nbase + tx * 8;
        const float* p2 = b2 + nbase + tx * 8;
#pragma unroll
        for (int j = 0; j < 8; j++) Cr[j] = acc[i][j] + p1[j] + p2[j];
    }
}

// ---------------- tree grid barrier (per-domain) -----------------------------
__device__ __forceinline__ void gsync3(int dom, int lidx, int leafsz, unsigned& lg) {
    __syncthreads();
    if (threadIdx.x == 0) {
        __threadfence();
        unsigned target = lg + 1;
        int leaf = lidx & 7;
        if (atomicAdd(&BAR_LEAF[(dom * 8 + leaf) * 32], 1u) == (unsigned)(leafsz - 1)) {
            atomicExch(&BAR_LEAF[(dom * 8 + leaf) * 32], 0u);
            if (atomicAdd(&BAR_ROOT[dom * 32], 1u) == 7u) {
                atomicExch(&BAR_ROOT[dom * 32], 0u);
                __threadfence();
                BAR_G2[dom] = target;
            }
        }
        while (BAR_G2[dom] < target) __nanosleep(32);
        __threadfence();
    }
    lg++;
    __syncthreads();
}

// ---------------- tensor-core persistent recurrence --------------------------
// bf16 hi/lo 3-pass mma; W_hh fragments resident in smem; h exchanged as bf16
// hi+lo planes; acc init = pre. Double-buffered staging: 1 syncthreads per
// k-chunk; STS(next) + LDG(next+1) issued BEFORE the current chunk's MMA so
// they drain underneath it.
#define MMA_BF16(C, A0, A1, A2, A3, B0, B1)                                   \
    asm volatile("mma.sync.aligned.m16n8k16.row.col.f32.bf16.bf16.f32 "       \
                 "{%0,%1,%2,%3}, {%4,%5,%6,%7}, {%8,%9}, {%0,%1,%2,%3};"      \
                 : "+f"((C)[0]), "+f"((C)[1]), "+f"((C)[2]), "+f"((C)[3])     \
                 : "r"(A0), "r"(A1), "r"(A2), "r"(A3), "r"(B0), "r"(B1))

struct RQ3 {
    const float* pre[2];
    const float* whh[2];
    __nv_bfloat16* hp[2];    // 4 planes: A_hi, A_lo, B_hi, B_lo (each BSZ*HSZ)
    float* out0[2];          // fp32, pre-offset by dir*512; nullptr = none
    float* hfin;             // fp32 final-h sink (l1 only)
    int rev[2];
    int ndirs;
};

template <int ROWS, int MT>
__global__ void __launch_bounds__(256, 1) k_recur3(RQ3 p) {
    constexpr int NW = ROWS / (16 * MT);     // mma warps (MT m-tiles each) = 4
    constexpr int SN = (ROWS == 128) ? 8 : 4;
    constexpr int BUFU = ROWS * 72;          // u32 per staging buffer (hi+lo)
    extern __shared__ unsigned sm[];
    unsigned* WF = sm;                        // [32 k16][4 gates][32 lanes][4] u32

    int tid = threadIdx.x;
    int wid = tid >> 5, lane = tid & 31;
    int lr = lane >> 2, lc = lane & 3;
    const int slab = BSZ * HSZ;

    int dir, j0, rbase, dom, lidx, leafsz;
    if (p.ndirs == 2) {
        dir = blockIdx.x >> 6; j0 = (blockIdx.x & 63) * 8; rbase = 0;
        dom = dir; lidx = blockIdx.x & 63; leafsz = 8;        // 64-block domain
    } else {
        dir = 0; j0 = (blockIdx.x >> 1) * 8; rbase = (blockIdx.x & 1) * 64;
        dom = 2; lidx = blockIdx.x; leafsz = 16;              // 128-block domain
    }

    const float* whh = p.whh[dir];
    const float* pre = p.pre[dir];
    __nv_bfloat16* hp = p.hp[dir];
    float* out0 = p.out0[dir];
    int rev = p.rev[dir];

    // ---- one-time W_hh -> bf16 hi/lo fragments in smem
    for (int e = tid; e < 4096; e += 256) {
        int ln   = e & 31;
        int g    = (e >> 5) & 3;
        int k16g = e >> 7;
        int jj   = ln >> 2;
        int kk   = k16g * 16 + (ln & 3) * 2;
        const float* wr = whh + (size_t)(g * 512 + j0 + jj) * 512 + kk;
        float w0 = wr[0], w1 = wr[1], w8 = wr[8], w9 = wr[9];
        float h0 = __bfloat162float(__float2bfloat16(w0));
        float h1 = __bfloat162float(__float2bfloat16(w1));
        float h8 = __bfloat162float(__float2bfloat16(w8));
        float h9 = __bfloat162float(__float2bfloat16(w9));
        unsigned* d = WF + (size_t)e * 4;
        d[0] = pack_bf16(w0, w1);
        d[1] = pack_bf16(w8, w9);
        d[2] = pack_bf16(w0 - h0, w1 - h1);
        d[3] = pack_bf16(w8 - h8, w9 - h9);
    }

    // staging assignment: (row, plane[, k-half])
    int srow, splane, sbase;
    if (ROWS == 128) { srow = tid & 127; splane = tid >> 7; sbase = 0; }
    else             { srow = tid & 63; splane = (tid >> 6) & 1; sbase = (tid >> 7) * 4; }
    unsigned* sdst0 = sm + 16384 + (splane ? ROWS * 36 : 0) + srow * 36;

    bool ismma = (wid < NW);
    int w = wid;

    float creg[MT][4], hreg[MT][4];
#pragma unroll
    for (int mt = 0; mt < MT; mt++)
#pragma unroll
        for (int q = 0; q < 4; q++) { creg[mt][q] = 1.0f; hreg[mt][q] = 1.0f; }

    __syncthreads();     // WF ready
    unsigned lg = 0;

    for (int s = 0; s < SSZ; s++) {
        int tt = rev ? (SSZ - 1 - s) : s;
        int nact = NACT[tt];
        int nloc = nact - rbase;
        const __nv_bfloat16* hinh = hp + ((s & 1) ? 2 : 0) * slab;
        const __nv_bfloat16* hinl = hp + ((s & 1) ? 3 : 1) * slab;
        __nv_bfloat16* houth = hp + ((s & 1) ? 0 : 2) * slab;
        __nv_bfloat16* houtl = hp + ((s & 1) ? 1 : 3) * slab;
        bool do_stage = (rbase + srow) < nact;

        // ---- acc init = pre (gate bias); LDGs drain under staging below
        float acc[MT][4][4];
        if (ismma) {
#pragma unroll
            for (int mt = 0; mt < MT; mt++) {
#pragma unroll
                for (int qh = 0; qh < 2; qh++) {
                    int row = rbase + w * (16 * MT) + mt * 16 + qh * 8 + lr;
                    const float* pb = pre + ((size_t)tt * BSZ + row) * G4 + j0 + 2 * lc;
                    bool a = row < nact;
#pragma unroll
                    for (int g = 0; g < 4; g++) {
                        float2 z = a ? *(const float2*)(pb + g * 512) : make_float2(0.f, 0.f);
                        acc[mt][g][qh * 2 + 0] = z.x;
                        acc[mt][g][qh * 2 + 1] = z.y;
                    }
                }
            }
        }

        const uint4* ssrc = (const uint4*)((splane ? hinl : hinh) +
                                           (size_t)(rbase + srow) * HSZ);
        uint4 stg[SN];
        // chunk 0: LDG + STS into buf 0 (block already synced by gsync3)
        if (do_stage) {
#pragma unroll
            for (int i = 0; i < SN; i++) stg[i] = ssrc[sbase + i];
            uint4* dst = (uint4*)sdst0;
#pragma unroll
            for (int i = 0; i < SN; i++) dst[sbase + i] = stg[i];
            // prefetch chunk 1
#pragma unroll
            for (int i = 0; i < SN; i++) stg[i] = ssrc[8 + sbase + i];
        }
        __syncthreads();          // buf0 ready

        for (int kc = 0; kc < 8; kc++) {
            int cur = kc & 1;
            // STS chunk kc+1 into the other buffer, LDG chunk kc+2 — both
            // issued BEFORE this chunk's MMA so they drain underneath it.
            if (kc + 1 < 8 && do_stage) {
                uint4* dst = (uint4*)(sdst0 + (cur ^ 1) * BUFU);
#pragma unroll
                for (int i = 0; i < SN; i++) dst[sbase + i] = stg[i];
                if (kc + 2 < 8) {
#pragma unroll
                    for (int i = 0; i < SN; i++) stg[i] = ssrc[(kc + 2) * 8 + sbase + i];
                }
            }
            if (ismma && w * (16 * MT) < nloc) {
                const unsigned* AHI = sm + 16384 + cur * BUFU;
                const unsigned* ALO = AHI + ROWS * 36;
#pragma unroll
                for (int k16l = 0; k16l < 4; k16l++) {
                    int k16g = kc * 4 + k16l;
                    const unsigned* wb = WF + ((size_t)k16g * 4) * 128 + lane * 4;
                    uint4 bf0 = *(const uint4*)(wb);
                    uint4 bf1 = *(const uint4*)(wb + 128);
                    uint4 bf2 = *(const uint4*)(wb + 256);
                    uint4 bf3 = *(const uint4*)(wb + 384);
                    int kw = k16l * 8 + lc;
#pragma unroll
                    for (int mt = 0; mt < MT; mt++) {
                        if (w * (16 * MT) + mt * 16 >= nloc) continue;
                        int rb0 = (w * (16 * MT) + mt * 16 + lr) * 36 + kw;
                        int rb1 = rb0 + 8 * 36;
                        unsigned a0h = AHI[rb0], a1h = AHI[rb1];
                        unsigned a2h = AHI[rb0 + 4], a3h = AHI[rb1 + 4];
                        unsigned a0l = ALO[rb0], a1l = ALO[rb1];
                        unsigned a2l = ALO[rb0 + 4], a3l = ALO[rb1 + 4];
                        MMA_BF16(acc[mt][0], a0h, a1h, a2h, a3h, bf0.x, bf0.y);
                        MMA_BF16(acc[mt][0], a0h, a1h, a2h, a3h, bf0.z, bf0.w);
                        MMA_BF16(acc[mt][0], a0l, a1l, a2l, a3l, bf0.x, bf0.y);
                        MMA_BF16(acc[mt][1], a0h, a1h, a2h, a3h, bf1.x, bf1.y);
                        MMA_BF16(acc[mt][1], a0h, a1h, a2h, a3h, bf1.z, bf1.w);
                        MMA_BF16(acc[mt][1], a0l, a1l, a2l, a3l, bf1.x, bf1.y);
                        MMA_BF16(acc[mt][2], a0h, a1h, a2h, a3h, bf2.x, bf2.y);
                        MMA_BF16(acc[mt][2], a0h, a1h, a2h, a3h, bf2.z, bf2.w);
                        MMA_BF16(acc[mt][2], a0l, a1l, a2l, a3l, bf2.x, bf2.y);
                        MMA_BF16(acc[mt][3], a0h, a1h, a2h, a3h, bf3.x, bf3.y);
                        MMA_BF16(acc[mt][3], a0h, a1h, a2h, a3h, bf3.z, bf3.w);
                        MMA_BF16(acc[mt][3], a0l, a1l, a2l, a3l, bf3.x, bf3.y);
                    }
                }
            }
            __syncthreads();   // STS(kc+1) visible; MMA(kc) done before buf reuse
        }

        // ---- gates (register-local: acc[mt][g][q] = 4 gates of cell q)
        if (ismma) {
#pragma unroll
            for (int mt = 0; mt < MT; mt++) {
#pragma unroll
                for (int qh = 0; qh < 2; qh++) {
                    int row = rbase + w * (16 * MT) + mt * 16 + qh * 8 + lr;
#pragma unroll
                    for (int qc = 0; qc < 2; qc++) {
                        int q = qh * 2 + qc;
                        if (row < nact) {
                            float zi = acc[mt][0][q], zf = acc[mt][1][q];
                            float zg = acc[mt][2][q], zo = acc[mt][3][q];
                            float cn = sigm(zf) * creg[mt][q] + sigm(zi) * tanhf(zg);
                            creg[mt][q] = cn;
                            hreg[mt][q] = sigm(zo) * tanhf(cn);
                        }
                    }
                    float h0 = hreg[mt][qh * 2], h1 = hreg[mt][qh * 2 + 1];
                    float h0h = __bfloat162float(__float2bfloat16(h0));
                    float h1h = __bfloat162float(__float2bfloat16(h1));
                    unsigned ph = pack_bf16(h0, h1);
                    unsigned pl = pack_bf16(h0 - h0h, h1 - h1h);
                    int cb = j0 + 2 * lc;
                    *(unsigned*)(houth + (size_t)row * HSZ + cb) = ph;
                    *(unsigned*)(houtl + (size_t)row * HSZ + cb) = pl;
                    if (out0) {
                        float2 o; o.x = h0; o.y = h1;
                        *(float2*)(out0 + ((size_t)tt * BSZ + row) * (2 * HSZ) + cb) = o;
                    }
                    if (p.hfin && s == SSZ - 1) {
                        float2 o; o.x = h0; o.y = h1;
                        *(float2*)(p.hfin + (size_t)row * HSZ + cb) = o;
                    }
                }
            }
        }
        gsync3(dom, lidx, leafsz, lg);
    }
}

// ---------------- FC head ----------------------------------------------------
__global__ void k_fc(const float* __restrict__ h,
                     const float* __restrict__ fc1w, const float* __restrict__ fc1b,
                     const float* __restrict__ fcw,  const float* __restrict__ fcb,
                     float* __restrict__ out)
{
    __shared__ float tmp[HSZ];
    __shared__ float red[2][256];
    int b = blockIdx.x, tid = threadIdx.x;
    const float* hb = h + (size_t)RANK[b] * HSZ;

    for (int j = tid; j < HSZ; j += 256) {
        const float* w = fc1w + (size_t)j * HSZ;
        float s0 = 0.f, s1 = 0.f, s2 = 0.f, s3 = 0.f;
        for (int k = 0; k < HSZ; k += 4) {
            s0 += hb[k] * w[k];         s1 += hb[k + 1] * w[k + 1];
            s2 += hb[k + 2] * w[k + 2]; s3 += hb[k + 3] * w[k + 3];
        }
        tmp[j] = s0 + s1 + s2 + s3 + fc1b[j];
    }
    __syncthreads();
    float p0 = 0.f, p1 = 0.f;
    for (int k = tid; k < HSZ; k += 256) {
        p0 += tmp[k] * fcw[k];
        p1 += tmp[k] * fcw[HSZ + k];
    }
    red[0][tid] = p0; red[1][tid] = p1;
    __syncthreads();
    for (int off = 128; off > 0; off >>= 1) {
        if (tid < off) {
            red[0][tid] += red[0][tid + off];
            red[1][tid] += red[1][tid + off];
        }
        __syncthreads();
    }
    if (tid == 0) {
        out[b * 2 + 0] = red[0][0] + fcb[0];
        out[b * 2 + 1] = red[1][0] + fcb[1];
    }
}

// ---------------- host launch sequence ---------------------------------------
extern "C" void kernel_launch(void* const* d_in, const int* in_sizes, int n_in,
                              void* d_out, int out_size)
{
    const float* x          = (const float*)d_in[0];
    const float* w_ih_l0_f  = (const float*)d_in[1];
    const float* w_hh_l0_f  = (const float*)d_in[2];
    const float* b_ih_l0_f  = (const float*)d_in[3];
    const float* b_hh_l0_f  = (const float*)d_in[4];
    const float* w_ih_l0_r  = (const float*)d_in[5];
    const float* w_hh_l0_r  = (const float*)d_in[6];
    const float* b_ih_l0_r  = (const float*)d_in[7];
    const float* b_hh_l0_r  = (const float*)d_in[8];
    // d_in[9..12] = layer-1 forward (dead code: reference uses only hT_r)
    const float* w_ih_l1_r  = (const float*)d_in[13];
    const float* w_hh_l1_r  = (const float*)d_in[14];
    const float* b_ih_l1_r  = (const float*)d_in[15];
    const float* b_hh_l1_r  = (const float*)d_in[16];
    const float* fc1_w      = (const float*)d_in[17];
    const float* fc1_b      = (const float*)d_in[18];
    const float* fc_w       = (const float*)d_in[19];
    const float* fc_b       = (const float*)d_in[20];
    float* out = (float*)d_out;

    void* pv;
    cudaGetSymbolAddress(&pv, PRE0F);  float* pre0f = (float*)pv;
    cudaGetSymbolAddress(&pv, PRE0R);  float* pre0r = (float*)pv;
    cudaGetSymbolAddress(&pv, OUT0);   float* out0  = (float*)pv;
    cudaGetSymbolAddress(&pv, HP);     __nv_bfloat16* hpb = (__nv_bfloat16*)pv;
    cudaGetSymbolAddress(&pv, HFIN);   float* hfin  = (float*)pv;
    float* pre1 = pre0f;               // alias: PRE0F dead after l0 recurrence
    const int slab = BSZ * HSZ;
    const int M = BSZ * SSZ;

    const int SMR0 = (16384 + 2 * 128 * 72) * 4;   // 139264 B
    const int SMR1 = (16384 + 2 * 64 * 72) * 4;    // 102400 B
    cudaFuncSetAttribute((const void*)k_recur3<128, 2>,
                         cudaFuncAttributeMaxDynamicSharedMemorySize, SMR0);
    cudaFuncSetAttribute((const void*)k_recur3<64, 1>,
                         cudaFuncAttributeMaxDynamicSharedMemorySize, SMR1);

    // 1) init + rank/NACT prep                                   (launch 1,2)
    k_init<<<768, 256>>>(x);
    k_prep<<<1, BSZ>>>();

    // 2) layer-0 input projections, fused fwd+rev (grid.z=2)     (launch 3)
    GP g0;
    g0.W[0] = w_ih_l0_f; g0.b1[0] = b_ih_l0_f; g0.b2[0] = b_hh_l0_f; g0.C[0] = pre0f;
    g0.W[1] = w_ih_l0_r; g0.b1[1] = b_ih_l0_r; g0.b2[1] = b_hh_l0_r; g0.C[1] = pre0r;
    k_gemm<<<dim3(16, 256, 2), 256>>>(x, M, ESZ, g0, 1);

    // 3) layer-0 recurrence (domains 0,1)                        (launch 4)
    RQ3 rq0;
    rq0.pre[0] = pre0f;  rq0.whh[0] = w_hh_l0_f;
    rq0.hp[0]  = hpb;                rq0.out0[0] = out0;        rq0.rev[0] = 0;
    rq0.pre[1] = pre0r;  rq0.whh[1] = w_hh_l0_r;
    rq0.hp[1]  = hpb + 4 * slab;     rq0.out0[1] = out0 + HSZ;  rq0.rev[1] = 1;
    rq0.hfin = nullptr;  rq0.ndirs = 2;
    k_recur3<128, 2><<<NB_RECUR, 256, SMR0>>>(rq0);

    // 4) layer-1 (reverse only) projection                       (launch 5)
    GP g1;
    g1.W[0] = w_ih_l1_r; g1.b1[0] = b_ih_l1_r; g1.b2[0] = b_hh_l1_r; g1.C[0] = pre1;
    g1.W[1] = w_ih_l1_r; g1.b1[1] = b_ih_l1_r; g1.b2[1] = b_hh_l1_r; g1.C[1] = pre1;
    k_gemm<<<dim3(16, 256, 1), 256>>>(out0, M, 2 * HSZ, g1, 2);

    // 5) layer-1 reverse recurrence (domain 2, no reset needed)  (launch 6)
    RQ3 rq1;
    rq1.pre[0] = pre1;   rq1.whh[0] = w_hh_l1_r;
    rq1.hp[0]  = hpb + 8 * slab;     rq1.out0[0] = nullptr;     rq1.rev[0] = 1;
    rq1.pre[1] = nullptr; rq1.whh[1] = nullptr;
    rq1.hp[1]  = nullptr;            rq1.out0[1] = nullptr;     rq1.rev[1] = 0;
    rq1.hfin = hfin;     rq1.ndirs = 1;
    k_recur3<64, 1><<<NB_RECUR, 256, SMR1>>>(rq1);

    // 6) FC head on fp32 final h (rank rows)                     (launch 7)
    k_fc<<<BSZ, 256>>>(hfin, fc1_w, fc1_b, fc_w, fc_b, out);
}

// round 17
// speedup vs baseline: 2.0856x; 1.0507x over previous
#include <cuda_runtime.h>
#include <cuda_bf16.h>
#include <math.h>

// Problem constants
#define BSZ 128
#define SSZ 256
#define ESZ 300
#define HSZ 512
#define G4  2048
#define NB_RECUR 128       // persistent grid: 1 block/SM, co-resident wave 1

// ---------------- scratch (static device memory) -----------------------------
__device__ float PRE0F[SSZ * BSZ * G4];          // [t][r][4H] l0 fwd (aliased: l1 rev)
__device__ float PRE0R[SSZ * BSZ * G4];          // [t][r][4H] l0 rev
// l0 output as bf16 hi/lo planes: [t][r][2H] each
__device__ __nv_bfloat16 OUT0H[SSZ * BSZ * 2 * HSZ];
__device__ __nv_bfloat16 OUT0L[SSZ * BSZ * 2 * HSZ];
// w_ih_l1_r pre-converted to bf16 hi/lo planes [2048][1024]
__device__ __nv_bfloat16 W1H[G4 * 2 * HSZ];
__device__ __nv_bfloat16 W1L[G4 * 2 * HSZ];
// h exchange planes (bf16): slot*4 + {A_hi, A_lo, B_hi, B_lo}; slots: l0f,l0r,l1r
__device__ __nv_bfloat16 HP[12][BSZ * HSZ];
__device__ float HFIN[BSZ * HSZ];                // fp32 final h of l1 (rank rows)
__device__ int   LEN[BSZ];
__device__ int   RANK[BSZ];
__device__ int   NACT[SSZ];
// tree barrier: 4 domains (l0f, l0r, l1h0, l1h1) x 8 leaves on own 128B lines
__device__ unsigned BAR_LEAF[4 * 8 * 32];
__device__ unsigned BAR_ROOT[4 * 32];
__device__ volatile unsigned BAR_G2[4];

__device__ __forceinline__ float sigm(float x) { return 1.0f / (1.0f + expf(-x)); }

__device__ __forceinline__ unsigned pack_bf16(float x, float y) {
    __nv_bfloat16 bx = __float2bfloat16(x), by = __float2bfloat16(y);
    return (unsigned)__bfloat16_as_ushort(bx) | ((unsigned)__bfloat16_as_ushort(by) << 16);
}

// ---------------- init ------------------------------------------------------
__global__ void k_init(const float* __restrict__ x) {
    int tid = blockIdx.x * blockDim.x + threadIdx.x;
    const int slab = BSZ * HSZ;
    if (tid < 3 * slab) {                 // h bufA planes: hi=1.0, lo=0
        int w = tid / slab, i = tid - w * slab;
        HP[w * 4 + 0][i] = __float2bfloat16(1.0f);
        HP[w * 4 + 1][i] = __float2bfloat16(0.0f);
    }
    if (tid < BSZ) {
        int v = (int)x[((size_t)tid * SSZ + (SSZ - 1)) * ESZ];
        LEN[tid] = v < SSZ ? v : SSZ;
    }
    if (tid < 1024) BAR_LEAF[tid] = 0;
    if (tid < 128)  BAR_ROOT[tid] = 0;
    if (tid < 4)    BAR_G2[tid] = 0;
}

// ---------------- prep: rank permutation + NACT ------------------------------
__global__ void k_prep() {
    __shared__ int sl[BSZ];
    int b = threadIdx.x;
    sl[b] = LEN[b];
    __syncthreads();
    int mylen = sl[b];
    int rk = 0;
    for (int o = 0; o < BSZ; o++) {
        int lo = sl[o];
        rk += (lo > mylen) || (lo == mylen && o < b);
    }
    RANK[b] = rk;
    for (int t = b; t < SSZ; t += BSZ) {
        int c = 0;
        for (int o = 0; o < BSZ; o++) c += (sl[o] > t);
        NACT[t] = c;
    }
}

// ---------------- one-shot W_ih_l1 fp32 -> bf16 hi/lo planes -----------------
__global__ void k_cvtw(const float* __restrict__ W) {
    int i = blockIdx.x * blockDim.x + threadIdx.x;
    int n = G4 * 2 * HSZ;
    if (i < n) {
        float w = W[i];
        __nv_bfloat16 h = __float2bfloat16(w);
        W1H[i] = h;
        W1L[i] = __float2bfloat16(w - __bfloat162float(h));
    }
}

// ---------------- fp32 NT-GEMM (layer-0 projections, fused fwd+rev) ----------
struct GP {
    const float* W[2];
    const float* b1[2];
    const float* b2[2];
    float* C[2];
};

__global__ void __launch_bounds__(256, 2) k_gemm(
    const float* __restrict__ A, int M, int K, GP gp)
{
    __shared__ float As[8][128];
    __shared__ float Bs[8][128];

    const float* W  = gp.W[blockIdx.z];
    const float* b1 = gp.b1[blockIdx.z];
    const float* b2 = gp.b2[blockIdx.z];
    float* C        = gp.C[blockIdx.z];

    int tid = threadIdx.x;
    int ty = tid >> 4, tx = tid & 15;
    int mbase = blockIdx.y * 128;
    int nbase = blockIdx.x * 128;

    // mode-1 row skip: tile spans one b
    int b = mbase >> 8, t0 = mbase & 255;
    int rowlim = LEN[b] - t0;
    if (rowlim > 128) rowlim = 128;
    if (rowlim <= 0) return;
    bool act = (ty * 8) < rowlim;

    float acc[8][8];
#pragma unroll
    for (int i = 0; i < 8; i++)
#pragma unroll
        for (int j = 0; j < 8; j++) acc[i][j] = 0.0f;

    int lrow = tid >> 1;
    int lk   = (tid & 1) * 4;
    const float* Arow = A + (size_t)(mbase + lrow) * K;
    const float* Wrow = W + (size_t)(nbase + lrow) * K;

    for (int kb = 0; kb < K; kb += 8) {
        float av[4], wv[4];
        if (kb + lk + 3 < K) {
            float4 t = *(const float4*)(Arow + kb + lk);
            av[0] = t.x; av[1] = t.y; av[2] = t.z; av[3] = t.w;
            float4 u = *(const float4*)(Wrow + kb + lk);
            wv[0] = u.x; wv[1] = u.y; wv[2] = u.z; wv[3] = u.w;
        } else {
#pragma unroll
            for (int i = 0; i < 4; i++) {
                int k = kb + lk + i;
                av[i] = (k < K) ? Arow[k] : 0.0f;
                wv[i] = (k < K) ? Wrow[k] : 0.0f;
            }
        }
        __syncthreads();
#pragma unroll
        for (int i = 0; i < 4; i++) {
            As[lk + i][lrow] = av[i];
            Bs[lk + i][lrow] = wv[i];
        }
        __syncthreads();
        if (act) {
#pragma unroll
            for (int kk = 0; kk < 8; kk++) {
                float a[8], bb[8];
                *(float4*)&a[0] = *(const float4*)&As[kk][ty * 8];
                *(float4*)&a[4] = *(const float4*)&As[kk][ty * 8 + 4];
                *(float4*)&bb[0] = *(const float4*)&Bs[kk][tx * 8];
                *(float4*)&bb[4] = *(const float4*)&Bs[kk][tx * 8 + 4];
#pragma unroll
                for (int i = 0; i < 8; i++)
#pragma unroll
                    for (int j = 0; j < 8; j++) acc[i][j] += a[i] * bb[j];
            }
        }
    }

#pragma unroll
    for (int i = 0; i < 8; i++) {
        int lr = ty * 8 + i;
        if (lr >= rowlim) continue;
        int m = mbase + lr;
        int crow = ((m & 255) << 7) + RANK[m >> 8];
        float* Cr = C + (size_t)crow * G4 + nbase + tx * 8;
        const float* p1 = b1 + nbase + tx * 8;
        const float* p2 = b2 + nbase + tx * 8;
#pragma unroll
        for (int j = 0; j < 8; j++) Cr[j] = acc[i][j] + p1[j] + p2[j];
    }
}

// ---------------- bf16 TC GEMM for layer-1 projection ------------------------
// C[M,2048] = A(hi/lo)[M,1024] x W(hi/lo)[2048,1024]^T + b1 + b2
// 3-pass hi/lo (Ahi*Whi + Ahi*Wlo + Alo*Whi). A/W pre-converted in global,
// staging = raw uint4 copies (stride-20 smem, conflict-free fragment loads).
#define MMA_BF16(C, A0, A1, A2, A3, B0, B1)                                   \
    asm volatile("mma.sync.aligned.m16n8k16.row.col.f32.bf16.bf16.f32 "       \
                 "{%0,%1,%2,%3}, {%4,%5,%6,%7}, {%8,%9}, {%0,%1,%2,%3};"      \
                 : "+f"((C)[0]), "+f"((C)[1]), "+f"((C)[2]), "+f"((C)[3])     \
                 : "r"(A0), "r"(A1), "r"(A2), "r"(A3), "r"(B0), "r"(B1))

__global__ void __launch_bounds__(256, 2) k_gemm_tc2(
    const float* __restrict__ b1, const float* __restrict__ b2,
    float* __restrict__ C)
{
    __shared__ unsigned Ah[128 * 20], Al[128 * 20];
    __shared__ unsigned Bh[64 * 20],  Bl[64 * 20];
    const int K = 2 * HSZ;   // 1024

    int tid  = threadIdx.x;
    int warp = tid >> 5, lane = tid & 31;
    int wm = warp >> 1, wn = warp & 1;          // 4 x 2 warp grid
    int lr = lane >> 2, lc = lane & 3;
    int mbase = blockIdx.y * 128;
    int nbase = blockIdx.x * 64;

    int t = mbase >> 7;
    int rowlim = NACT[t];
    if (rowlim <= 0) return;
    bool wact = (wm * 32) < rowlim;

    float acc[2][4][4];
#pragma unroll
    for (int i = 0; i < 2; i++)
#pragma unroll
        for (int j = 0; j < 4; j++)
#pragma unroll
            for (int q = 0; q < 4; q++) acc[i][j][q] = 0.0f;

    // staging assignments (pure copies)
    int arow = tid >> 1, ak = (tid & 1) * 16;       // 16 bf16 = 2 uint4 / plane
    int brow = tid & 63, bk = (tid >> 6) * 8;       // 8 bf16 = 1 uint4 / plane
    const uint4* pah = (const uint4*)(OUT0H + (size_t)(mbase + arow) * K);
    const uint4* pal = (const uint4*)(OUT0L + (size_t)(mbase + arow) * K);
    const uint4* pwh = (const uint4*)(W1H + (size_t)(nbase + brow) * K);
    const uint4* pwl = (const uint4*)(W1L + (size_t)(nbase + brow) * K);

    // prefetch k-block 0
    uint4 rah0 = pah[ak / 8],     rah1 = pah[ak / 8 + 1];
    uint4 ral0 = pal[ak / 8],     ral1 = pal[ak / 8 + 1];
    uint4 rwh  = pwh[bk / 8],     rwl  = pwl[bk / 8];

    for (int kb = 0; kb < K; kb += 32) {
        __syncthreads();
        // ---- STS current block (aligned: 20r % 4 == 0)
        *(uint4*)(Ah + arow * 20 + ak / 2)     = rah0;
        *(uint4*)(Ah + arow * 20 + ak / 2 + 4) = rah1;
        *(uint4*)(Al + arow * 20 + ak / 2)     = ral0;
        *(uint4*)(Al + arow * 20 + ak / 2 + 4) = ral1;
        *(uint4*)(Bh + brow * 20 + bk / 2)     = rwh;
        *(uint4*)(Bl + brow * 20 + bk / 2)     = rwl;
        __syncthreads();
        // ---- LDG next block (drains under MMA)
        if (kb + 32 < K) {
            int kn = (kb + 32 + ak) / 8;
            rah0 = pah[kn]; rah1 = pah[kn + 1];
            ral0 = pal[kn]; ral1 = pal[kn + 1];
            int kbn = (kb + 32 + bk) / 8;
            rwh = pwh[kbn]; rwl = pwl[kbn];
        }
        if (!wact) continue;
        // ---- compute: 2 k16 steps per k-block (R11 fragment conventions)
#pragma unroll
        for (int kt = 0; kt < 2; kt++) {
            int kp = kt * 8 + lc;
            unsigned ah[2][4], al[2][4];
#pragma unroll
            for (int mt = 0; mt < 2; mt++) {
                int rb = wm * 32 + mt * 16;
                ah[mt][0] = Ah[(rb + lr)     * 20 + kp];
                ah[mt][1] = Ah[(rb + 8 + lr) * 20 + kp];
                ah[mt][2] = Ah[(rb + lr)     * 20 + kp + 4];
                ah[mt][3] = Ah[(rb + 8 + lr) * 20 + kp + 4];
                al[mt][0] = Al[(rb + lr)     * 20 + kp];
                al[mt][1] = Al[(rb + 8 + lr) * 20 + kp];
                al[mt][2] = Al[(rb + lr)     * 20 + kp + 4];
                al[mt][3] = Al[(rb + 8 + lr) * 20 + kp + 4];
            }
#pragma unroll
            for (int nt = 0; nt < 4; nt++) {
                int nb = wn * 32 + nt * 8;
                unsigned bh0 = Bh[(nb + lr) * 20 + kp];
                unsigned bh1 = Bh[(nb + lr) * 20 + kp + 4];
                unsigned bl0 = Bl[(nb + lr) * 20 + kp];
                unsigned bl1 = Bl[(nb + lr) * 20 + kp + 4];
#pragma unroll
                for (int mt = 0; mt < 2; mt++) {
                    MMA_BF16(acc[mt][nt], ah[mt][0], ah[mt][1], ah[mt][2], ah[mt][3], bh0, bh1);
                    MMA_BF16(acc[mt][nt], ah[mt][0], ah[mt][1], ah[mt][2], ah[mt][3], bl0, bl1);
                    MMA_BF16(acc[mt][nt], al[mt][0], al[mt][1], al[mt][2], al[mt][3], bh0, bh1);
                }
            }
        }
    }

    // ---- store with bias (active rows only)
#pragma unroll
    for (int mt = 0; mt < 2; mt++) {
#pragma unroll
        for (int nt = 0; nt < 4; nt++) {
            int col = nbase + wn * 32 + nt * 8 + lc * 2;
            float bia0 = b1[col] + b2[col];
            float bia1 = b1[col + 1] + b2[col + 1];
#pragma unroll
            for (int h = 0; h < 2; h++) {
                int lrow = wm * 32 + mt * 16 + h * 8 + lr;
                if (lrow >= rowlim) continue;
                int m = mbase + lrow;
                float* Cr = C + (size_t)m * G4 + col;
                Cr[0] = acc[mt][nt][h * 2]     + bia0;
                Cr[1] = acc[mt][nt][h * 2 + 1] + bia1;
            }
        }
    }
}

// ---------------- tree grid barrier (per-domain, 64 blocks, 8 leaves) --------
__device__ __forceinline__ void gsync3(int dom, int lidx, unsigned& lg) {
    __syncthreads();
    if (threadIdx.x == 0) {
        __threadfence();
        unsigned target = lg + 1;
        int leaf = lidx & 7;
        if (atomicAdd(&BAR_LEAF[(dom * 8 + leaf) * 32], 1u) == 7u) {
            atomicExch(&BAR_LEAF[(dom * 8 + leaf) * 32], 0u);
            if (atomicAdd(&BAR_ROOT[dom * 32], 1u) == 7u) {
                atomicExch(&BAR_ROOT[dom * 32], 0u);
                __threadfence();
                BAR_G2[dom] = target;
            }
        }
        while (BAR_G2[dom] < target) __nanosleep(32);
        __threadfence();
    }
    lg++;
    __syncthreads();
}

// ---------------- tensor-core persistent recurrence --------------------------
struct RQ3 {
    const float* pre[2];
    const float* whh[2];
    __nv_bfloat16* hp[2];    // 4 planes: A_hi, A_lo, B_hi, B_lo (each BSZ*HSZ)
    __nv_bfloat16* o0h[2];   // out planes, pre-offset by dir*512; nullptr = none
    __nv_bfloat16* o0l[2];
    float* hfin;             // fp32 final-h sink (l1 only)
    int rev[2];
    int ndirs;
};

template <int ROWS, int MT>
__global__ void __launch_bounds__(256, 1) k_recur3(RQ3 p) {
    constexpr int NW = ROWS / (16 * MT);
    constexpr int SN = (ROWS == 128) ? 8 : 4;
    constexpr int BUFU = ROWS * 72;          // u32 per staging buffer (hi+lo)
    extern __shared__ unsigned sm[];
    unsigned* WF = sm;                        // [32 k16][4 gates][32 lanes][4] u32

    int tid = threadIdx.x;
    int wid = tid >> 5, lane = tid & 31;
    int lr = lane >> 2, lc = lane & 3;
    const int slab = BSZ * HSZ;

    int dir, j0, rbase, dom, lidx;
    if (p.ndirs == 2) {
        dir = blockIdx.x >> 6; j0 = (blockIdx.x & 63) * 8; rbase = 0;
        dom = dir; lidx = blockIdx.x & 63;                    // 64-block domain
    } else {
        dir = 0; j0 = (blockIdx.x >> 1) * 8; rbase = (blockIdx.x & 1) * 64;
        dom = 2 + (blockIdx.x & 1); lidx = blockIdx.x >> 1;   // 2 x 64-block domains
    }

    const float* whh = p.whh[dir];
    const float* pre = p.pre[dir];
    __nv_bfloat16* hp = p.hp[dir];
    __nv_bfloat16* o0h = p.o0h[dir];
    __nv_bfloat16* o0l = p.o0l[dir];
    int rev = p.rev[dir];

    // ---- one-time W_hh -> bf16 hi/lo fragments in smem
    for (int e = tid; e < 4096; e += 256) {
        int ln   = e & 31;
        int g    = (e >> 5) & 3;
        int k16g = e >> 7;
        int jj   = ln >> 2;
        int kk   = k16g * 16 + (ln & 3) * 2;
        const float* wr = whh + (size_t)(g * 512 + j0 + jj) * 512 + kk;
        float w0 = wr[0], w1 = wr[1], w8 = wr[8], w9 = wr[9];
        float h0 = __bfloat162float(__float2bfloat16(w0));
        float h1 = __bfloat162float(__float2bfloat16(w1));
        float h8 = __bfloat162float(__float2bfloat16(w8));
        float h9 = __bfloat162float(__float2bfloat16(w9));
        unsigned* d = WF + (size_t)e * 4;
        d[0] = pack_bf16(w0, w1);
        d[1] = pack_bf16(w8, w9);
        d[2] = pack_bf16(w0 - h0, w1 - h1);
        d[3] = pack_bf16(w8 - h8, w9 - h9);
    }

    // staging assignment: (row, plane[, k-half])
    int srow, splane, sbase;
    if (ROWS == 128) { srow = tid & 127; splane = tid >> 7; sbase = 0; }
    else             { srow = tid & 63; splane = (tid >> 6) & 1; sbase = (tid >> 7) * 4; }
    unsigned* sdst0 = sm + 16384 + (splane ? ROWS * 36 : 0) + srow * 36;

    bool ismma = (wid < NW);
    int w = wid;

    float creg[MT][4], hreg[MT][4];
#pragma unroll
    for (int mt = 0; mt < MT; mt++)
#pragma unroll
        for (int q = 0; q < 4; q++) { creg[mt][q] = 1.0f; hreg[mt][q] = 1.0f; }

    __syncthreads();     // WF ready
    unsigned lg = 0;

    for (int s = 0; s < SSZ; s++) {
        int tt = rev ? (SSZ - 1 - s) : s;
        int nact = NACT[tt];
        int nloc = nact - rbase;
        const __nv_bfloat16* hinh = hp + ((s & 1) ? 2 : 0) * slab;
        const __nv_bfloat16* hinl = hp + ((s & 1) ? 3 : 1) * slab;
        __nv_bfloat16* houth = hp + ((s & 1) ? 0 : 2) * slab;
        __nv_bfloat16* houtl = hp + ((s & 1) ? 1 : 3) * slab;
        bool do_stage = (rbase + srow) < nact;

        // ---- acc init = pre (gate bias); LDGs drain under staging below
        float acc[MT][4][4];
        if (ismma) {
#pragma unroll
            for (int mt = 0; mt < MT; mt++) {
#pragma unroll
                for (int qh = 0; qh < 2; qh++) {
                    int row = rbase + w * (16 * MT) + mt * 16 + qh * 8 + lr;
                    const float* pb = pre + ((size_t)tt * BSZ + row) * G4 + j0 + 2 * lc;
                    bool a = row < nact;
#pragma unroll
                    for (int g = 0; g < 4; g++) {
                        float2 z = a ? *(const float2*)(pb + g * 512) : make_float2(0.f, 0.f);
                        acc[mt][g][qh * 2 + 0] = z.x;
                        acc[mt][g][qh * 2 + 1] = z.y;
                    }
                }
            }
        }

        const uint4* ssrc = (const uint4*)((splane ? hinl : hinh) +
                                           (size_t)(rbase + srow) * HSZ);
        uint4 stg[SN];
        // chunk 0: LDG + STS into buf 0 (block already synced by gsync3)
        if (do_stage) {
#pragma unroll
            for (int i = 0; i < SN; i++) stg[i] = ssrc[sbase + i];
            uint4* dst = (uint4*)sdst0;
#pragma unroll
            for (int i = 0; i < SN; i++) dst[sbase + i] = stg[i];
#pragma unroll
            for (int i = 0; i < SN; i++) stg[i] = ssrc[8 + sbase + i];
        }
        __syncthreads();          // buf0 ready

        for (int kc = 0; kc < 8; kc++) {
            int cur = kc & 1;
            if (kc + 1 < 8 && do_stage) {
                uint4* dst = (uint4*)(sdst0 + (cur ^ 1) * BUFU);
#pragma unroll
                for (int i = 0; i < SN; i++) dst[sbase + i] = stg[i];
                if (kc + 2 < 8) {
#pragma unroll
                    for (int i = 0; i < SN; i++) stg[i] = ssrc[(kc + 2) * 8 + sbase + i];
                }
            }
            if (ismma && w * (16 * MT) < nloc) {
                const unsigned* AHI = sm + 16384 + cur * BUFU;
                const unsigned* ALO = AHI + ROWS * 36;
#pragma unroll
                for (int k16l = 0; k16l < 4; k16l++) {
                    int k16g = kc * 4 + k16l;
                    const unsigned* wb = WF + ((size_t)k16g * 4) * 128 + lane * 4;
                    uint4 bf0 = *(const uint4*)(wb);
                    uint4 bf1 = *(const uint4*)(wb + 128);
                    uint4 bf2 = *(const uint4*)(wb + 256);
                    uint4 bf3 = *(const uint4*)(wb + 384);
                    int kw = k16l * 8 + lc;
#pragma unroll
                    for (int mt = 0; mt < MT; mt++) {
                        if (w * (16 * MT) + mt * 16 >= nloc) continue;
                        int rb0 = (w * (16 * MT) + mt * 16 + lr) * 36 + kw;
                        int rb1 = rb0 + 8 * 36;
                        unsigned a0h = AHI[rb0], a1h = AHI[rb1];
                        unsigned a2h = AHI[rb0 + 4], a3h = AHI[rb1 + 4];
                        unsigned a0l = ALO[rb0], a1l = ALO[rb1];
                        unsigned a2l = ALO[rb0 + 4], a3l = ALO[rb1 + 4];
                        MMA_BF16(acc[mt][0], a0h, a1h, a2h, a3h, bf0.x, bf0.y);
                        MMA_BF16(acc[mt][0], a0h, a1h, a2h, a3h, bf0.z, bf0.w);
                        MMA_BF16(acc[mt][0], a0l, a1l, a2l, a3l, bf0.x, bf0.y);
                        MMA_BF16(acc[mt][1], a0h, a1h, a2h, a3h, bf1.x, bf1.y);
                        MMA_BF16(acc[mt][1], a0h, a1h, a2h, a3h, bf1.z, bf1.w);
                        MMA_BF16(acc[mt][1], a0l, a1l, a2l, a3l, bf1.x, bf1.y);
                        MMA_BF16(acc[mt][2], a0h, a1h, a2h, a3h, bf2.x, bf2.y);
                        MMA_BF16(acc[mt][2], a0h, a1h, a2h, a3h, bf2.z, bf2.w);
                        MMA_BF16(acc[mt][2], a0l, a1l, a2l, a3l, bf2.x, bf2.y);
                        MMA_BF16(acc[mt][3], a0h, a1h, a2h, a3h, bf3.x, bf3.y);
                        MMA_BF16(acc[mt][3], a0h, a1h, a2h, a3h, bf3.z, bf3.w);
                        MMA_BF16(acc[mt][3], a0l, a1l, a2l, a3l, bf3.x, bf3.y);
                    }
                }
            }
            __syncthreads();
        }

        // ---- gates (register-local)
        if (ismma) {
#pragma unroll
            for (int mt = 0; mt < MT; mt++) {
#pragma unroll
                for (int qh = 0; qh < 2; qh++) {
                    int row = rbase + w * (16 * MT) + mt * 16 + qh * 8 + lr;
#pragma unroll
                    for (int qc = 0; qc < 2; qc++) {
                        int q = qh * 2 + qc;
                        if (row < nact) {
                            float zi = acc[mt][0][q], zf = acc[mt][1][q];
                            float zg = acc[mt][2][q], zo = acc[mt][3][q];
                            float cn = sigm(zf) * creg[mt][q] + sigm(zi) * tanhf(zg);
                            creg[mt][q] = cn;
                            hreg[mt][q] = sigm(zo) * tanhf(cn);
                        }
                    }
                    float h0 = hreg[mt][qh * 2], h1 = hreg[mt][qh * 2 + 1];
                    float h0h = __bfloat162float(__float2bfloat16(h0));
                    float h1h = __bfloat162float(__float2bfloat16(h1));
                    unsigned ph = pack_bf16(h0, h1);
                    unsigned pl = pack_bf16(h0 - h0h, h1 - h1h);
                    int cb = j0 + 2 * lc;
                    *(unsigned*)(houth + (size_t)row * HSZ + cb) = ph;
                    *(unsigned*)(houtl + (size_t)row * HSZ + cb) = pl;
                    if (o0h) {
                        size_t oidx = ((size_t)tt * BSZ + row) * (2 * HSZ) + cb;
                        *(unsigned*)(o0h + oidx) = ph;
                        *(unsigned*)(o0l + oidx) = pl;
                    }
                    if (p.hfin && s == SSZ - 1) {
                        float2 o; o.x = h0; o.y = h1;
                        *(float2*)(p.hfin + (size_t)row * HSZ + cb) = o;
                    }
                }
            }
        }
        gsync3(dom, lidx, lg);
    }
}

// ---------------- FC head ----------------------------------------------------
__global__ void k_fc(const float* __restrict__ h,
                     const float* __restrict__ fc1w, const float* __restrict__ fc1b,
                     const float* __restrict__ fcw,  const float* __restrict__ fcb,
                     float* __restrict__ out)
{
    __shared__ float tmp[HSZ];
    __shared__ float red[2][256];
    int b = blockIdx.x, tid = threadIdx.x;
    const float* hb = h + (size_t)RANK[b] * HSZ;

    for (int j = tid; j < HSZ; j += 256) {
        const float* w = fc1w + (size_t)j * HSZ;
        float s0 = 0.f, s1 = 0.f, s2 = 0.f, s3 = 0.f;
        for (int k = 0; k < HSZ; k += 4) {
            s0 += hb[k] * w[k];         s1 += hb[k + 1] * w[k + 1];
            s2 += hb[k + 2] * w[k + 2]; s3 += hb[k + 3] * w[k + 3];
        }
        tmp[j] = s0 + s1 + s2 + s3 + fc1b[j];
    }
    __syncthreads();
    float p0 = 0.f, p1 = 0.f;
    for (int k = tid; k < HSZ; k += 256) {
        p0 += tmp[k] * fcw[k];
        p1 += tmp[k] * fcw[HSZ + k];
    }
    red[0][tid] = p0; red[1][tid] = p1;
    __syncthreads();
    for (int off = 128; off > 0; off >>= 1) {
        if (tid < off) {
            red[0][tid] += red[0][tid + off];
            red[1][tid] += red[1][tid + off];
        }
        __syncthreads();
    }
    if (tid == 0) {
        out[b * 2 + 0] = red[0][0] + fcb[0];
        out[b * 2 + 1] = red[1][0] + fcb[1];
    }
}

// ---------------- host launch sequence ---------------------------------------
extern "C" void kernel_launch(void* const* d_in, const int* in_sizes, int n_in,
                              void* d_out, int out_size)
{
    const float* x          = (const float*)d_in[0];
    const float* w_ih_l0_f  = (const float*)d_in[1];
    const float* w_hh_l0_f  = (const float*)d_in[2];
    const float* b_ih_l0_f  = (const float*)d_in[3];
    const float* b_hh_l0_f  = (const float*)d_in[4];
    const float* w_ih_l0_r  = (const float*)d_in[5];
    const float* w_hh_l0_r  = (const float*)d_in[6];
    const float* b_ih_l0_r  = (const float*)d_in[7];
    const float* b_hh_l0_r  = (const float*)d_in[8];
    // d_in[9..12] = layer-1 forward (dead code: reference uses only hT_r)
    const float* w_ih_l1_r  = (const float*)d_in[13];
    const float* w_hh_l1_r  = (const float*)d_in[14];
    const float* b_ih_l1_r  = (const float*)d_in[15];
    const float* b_hh_l1_r  = (const float*)d_in[16];
    const float* fc1_w      = (const float*)d_in[17];
    const float* fc1_b      = (const float*)d_in[18];
    const float* fc_w       = (const float*)d_in[19];
    const float* fc_b       = (const float*)d_in[20];
    float* out = (float*)d_out;

    void* pv;
    cudaGetSymbolAddress(&pv, PRE0F);  float* pre0f = (float*)pv;
    cudaGetSymbolAddress(&pv, PRE0R);  float* pre0r = (float*)pv;
    cudaGetSymbolAddress(&pv, OUT0H);  __nv_bfloat16* o0h = (__nv_bfloat16*)pv;
    cudaGetSymbolAddress(&pv, OUT0L);  __nv_bfloat16* o0l = (__nv_bfloat16*)pv;
    cudaGetSymbolAddress(&pv, HP);     __nv_bfloat16* hpb = (__nv_bfloat16*)pv;
    cudaGetSymbolAddress(&pv, HFIN);   float* hfin  = (float*)pv;
    float* pre1 = pre0f;               // alias: PRE0F dead after l0 recurrence
    const int slab = BSZ * HSZ;
    const int M = BSZ * SSZ;

    const int SMR0 = (16384 + 2 * 128 * 72) * 4;   // 139264 B
    const int SMR1 = (16384 + 2 * 64 * 72) * 4;    // 102400 B
    cudaFuncSetAttribute((const void*)k_recur3<128, 2>,
                         cudaFuncAttributeMaxDynamicSharedMemorySize, SMR0);
    cudaFuncSetAttribute((const void*)k_recur3<64, 1>,
                         cudaFuncAttributeMaxDynamicSharedMemorySize, SMR1);

    // 1) init + rank/NACT prep                                   (launch 1,2)
    k_init<<<768, 256>>>(x);
    k_prep<<<1, BSZ>>>();

    // 2) layer-0 input projections, fused fwd+rev (grid.z=2)     (launch 3)
    GP g0;
    g0.W[0] = w_ih_l0_f; g0.b1[0] = b_ih_l0_f; g0.b2[0] = b_hh_l0_f; g0.C[0] = pre0f;
    g0.W[1] = w_ih_l0_r; g0.b1[1] = b_ih_l0_r; g0.b2[1] = b_hh_l0_r; g0.C[1] = pre0r;
    k_gemm<<<dim3(16, 256, 2), 256>>>(x, M, ESZ, g0);

    // 3) layer-0 recurrence (domains 0,1)                        (launch 4)
    RQ3 rq0;
    rq0.pre[0] = pre0f;  rq0.whh[0] = w_hh_l0_f;
    rq0.hp[0]  = hpb;                rq0.o0h[0] = o0h;        rq0.o0l[0] = o0l;
    rq0.rev[0] = 0;
    rq0.pre[1] = pre0r;  rq0.whh[1] = w_hh_l0_r;
    rq0.hp[1]  = hpb + 4 * slab;     rq0.o0h[1] = o0h + HSZ;  rq0.o0l[1] = o0l + HSZ;
    rq0.rev[1] = 1;
    rq0.hfin = nullptr;  rq0.ndirs = 2;
    k_recur3<128, 2><<<NB_RECUR, 256, SMR0>>>(rq0);

    // 4) W_ih_l1 -> bf16 planes (one-shot)                       (launch 5)
    k_cvtw<<<8192, 256>>>(w_ih_l1_r);

    // 5) layer-1 projection: pure-bf16 TC GEMM                   (launch 6)
    k_gemm_tc2<<<dim3(32, 256), 256>>>(b_ih_l1_r, b_hh_l1_r, pre1);

    // 6) layer-1 reverse recurrence (domains 2,3 by row half)    (launch 7)
    RQ3 rq1;
    rq1.pre[0] = pre1;   rq1.whh[0] = w_hh_l1_r;
    rq1.hp[0]  = hpb + 8 * slab;     rq1.o0h[0] = nullptr;    rq1.o0l[0] = nullptr;
    rq1.rev[0] = 1;
    rq1.pre[1] = nullptr; rq1.whh[1] = nullptr;
    rq1.hp[1]  = nullptr;            rq1.o0h[1] = nullptr;    rq1.o0l[1] = nullptr;
    rq1.rev[1] = 0;
    rq1.hfin = hfin;     rq1.ndirs = 1;
    k_recur3<64, 1><<<NB_RECUR, 256, SMR1>>>(rq1);

    // 7) FC head on fp32 final h (rank rows)                     (launch 8)
    k_fc<<<BSZ, 256>>>(hfin, fc1_w, fc1_b, fc_w, fc_b, out);
}